// round 10
// baseline (speedup 1.0000x reference)
#include <cuda_runtime.h>
#include <math.h>

#define NN 8192
#define NEI 8
#define NE (NN*NEI)
#define EPSV 1e-5f

// ---------------- scratch (static device memory; no runtime alloc) -------------
__device__ float4 g_posq[NN];    // (x, y, z, |p|^2) fp32 (query side)
__device__ float4 g_posq2[NN];   // (2x, 2y, 2z, |p|^2) fp32 (candidate side)
__device__ int    g_nbr[NE];
__device__ float  g_sh2[NE*5];
__device__ int    g_cnt[NN];
__device__ int    g_rowptr[NN+1];
__device__ int    g_cursor[NN];
__device__ int    g_csr[NE];
__device__ float  g_x0[NN*32];
__device__ float  g_x1[NN*48];
__device__ float  g_x2[NN*40];
__device__ float  g_y0[NN*32];
__device__ float  g_y1[NN*48];
__device__ float  g_y2[NN*40];
__device__ float  g_K[405];
__device__ float  g_scale0[32], g_shift0[32], g_scale1[16], g_scale2[8];

// K tensor layout offsets ([o][i][j] row-major per path)
// paths: (0,0,0)@0 sz1 | (0,2,2)@1 sz25 | (1,0,1)@26 sz9 | (1,2,1)@35 sz45 |
// (1,2,2)@80 sz75 | (2,0,2)@155 sz25 | (2,2,0)@180 sz25 | (2,2,1)@205 sz75 | (2,2,2)@280 sz125

// ---------------- K tensor init (fp32) -----------------------------------------
__device__ float ffact(int n){ float r=1.f; for(int i=2;i<=n;i++) r*=(float)i; return r; }

__device__ float cg_coef_f(int j1,int m1,int j2,int m2,int j3,int m3){
  if(m1+m2!=m3 || j3<abs(j1-j2) || j3>j1+j2) return 0.f;
  float pre = sqrtf((2.f*j3+1.f)*ffact(j3+j1-j2)*ffact(j3-j1+j2)*ffact(j1+j2-j3)/ffact(j1+j2+j3+1));
  pre *= sqrtf(ffact(j3+m3)*ffact(j3-m3)*ffact(j1-m1)*ffact(j1+m1)*ffact(j2-m2)*ffact(j2+m2));
  float s=0.f;
  for(int k=0;k<=j1+j2-j3;k++){
    int d0=k, d1=j1+j2-j3-k, d2=j1-m1-k, d3=j2+m2-k, d4=j3-j2+m1+k, d5=j3-j1-m2+k;
    if(d0<0||d1<0||d2<0||d3<0||d4<0||d5<0) continue;
    float den = ffact(d0)*ffact(d1)*ffact(d2)*ffact(d3)*ffact(d4)*ffact(d5);
    s += ((k&1)? -1.f:1.f)/den;
  }
  return pre*s;
}

__device__ void q_entry_f(int l,int r,int c,float* re,float* im){
  int a=r-l, b=c-l; *re=0.f; *im=0.f;
  if(a==0 && b==0){ *re=1.f; return; }
  if(abs(a)!=abs(b) || a==0 || b==0) return;
  int m=abs(a); float s=0.70710678118654752f; float sgn=(m&1)? -1.f:1.f;
  if(a==m && b==m)       *re = sgn*s;
  else if(a==m && b==-m) *re = s;
  else if(a==-m && b==m) *im = -sgn*s;
  else                   *im = s;
}

__global__ void k_initK(){
  const int L1[9]={0,0,1,1,1,2,2,2,2};
  const int L2[9]={0,2,0,2,2,0,2,2,2};
  const int L3[9]={0,2,1,1,2,2,0,1,2};
  const int OFF[9]={0,1,26,35,80,155,180,205,280};
  int p=blockIdx.x, t=threadIdx.x;
  int l1=L1[p], l2=L2[p], l3=L3[p];
  int d1=2*l1+1, d2=2*l2+1, d3=2*l3+1;
  int tot=d1*d2*d3;
  __shared__ float s_re[125], s_im[125];
  __shared__ int s_useim;
  float re=0.f, im=0.f;
  if(t<tot){
    int c=t/(d1*d2); int rem=t-(c*d1*d2); int a=rem/d2; int b=rem-a*d2;
    for(int C=0;C<d3;C++){
      float q3r,q3i; q_entry_f(l3,c,C,&q3r,&q3i); q3i=-q3i;  // conj
      if(q3r==0.f && q3i==0.f) continue;
      for(int A=0;A<d1;A++){
        float q1r,q1i; q_entry_f(l1,a,A,&q1r,&q1i);
        if(q1r==0.f && q1i==0.f) continue;
        for(int B=0;B<d2;B++){
          float q2r,q2i; q_entry_f(l2,b,B,&q2r,&q2i);
          if(q2r==0.f && q2i==0.f) continue;
          float cgv = cg_coef_f(l1,A-l1,l2,B-l2,l3,C-l3);
          if(cgv==0.f) continue;
          float xr=q3r*q1r-q3i*q1i, xi=q3r*q1i+q3i*q1r;
          float yr=xr*q2r-xi*q2i,  yi=xr*q2i+xi*q2r;
          re += yr*cgv; im += yi*cgv;
        }
      }
    }
    s_re[t]=re; s_im[t]=im;
  }
  __syncthreads();
  if(t==0){
    float mr=0.f, mi=0.f;
    for(int k=0;k<tot;k++){ mr=fmaxf(mr,fabsf(s_re[k])); mi=fmaxf(mi,fabsf(s_im[k])); }
    s_useim = (mi>mr)?1:0;
  }
  __syncthreads();
  if(t<tot) g_K[OFF[p]+t] = s_useim ? s_im[t] : s_re[t];
}

// ---------------- prep (posq + cnt + x init, fused) -------------------------
__global__ void k_prep(const float* __restrict__ pos, const float* __restrict__ W_emb){
  int t=blockIdx.x*blockDim.x+threadIdx.x;
  if(t<NN){
    float x=pos[t*3+0], y=pos[t*3+1], z=pos[t*3+2];
    float sq = __fadd_rn(__fadd_rn(__fmul_rn(x,x),__fmul_rn(y,y)),__fmul_rn(z,z));
    float4 q;  q.x=x;      q.y=y;      q.z=z;      q.w=sq;  g_posq[t]=q;
    float4 q2; q2.x=2.f*x; q2.y=2.f*y; q2.z=2.f*z; q2.w=sq; g_posq2[t]=q2;
    g_cnt[t]=0;
  }
  if(t < NN*32)       g_x0[t] = W_emb[t & 31];
  else if(t < NN*80)  g_x1[t-NN*32] = 0.f;
  else if(t < NN*120) g_x2[t-NN*80] = 0.f;
}

// ---------------- KNN: warp-cooperative replicated top-9 ---------------------
// d2 bit-pattern frozen (matches reference). Candidate coords pre-scaled by 2
// (exact), so the fmaf chain produces 2*dot bit-exactly.
__device__ __forceinline__ void topk_insert(float (&bv)[9], int (&bi)[9], float v, int j){
  float cv=v; int ci=j;
  #pragma unroll
  for(int k=0;k<9;k++){
    bool sw = (cv<bv[k]) || (cv==bv[k] && ci<bi[k]);
    float tv=bv[k]; int ti=bi[k];
    if(sw){ bv[k]=cv; bi[k]=ci; cv=tv; ci=ti; }
  }
}

__global__ void __launch_bounds__(256) k_knn(){
  int warp = threadIdx.x>>5, lane = threadIdx.x&31;
  int i = blockIdx.x*8 + warp;
  float4 q = g_posq[i];
  float bv[9]; int bi[9];
  #pragma unroll
  for(int k=0;k<9;k++){ bv[k]=INFINITY; bi[k]=0x7fffffff; }
  __shared__ float4 tile[256];
  for(int jt=0; jt<NN; jt+=256){
    __syncthreads();
    tile[threadIdx.x] = g_posq2[jt+threadIdx.x];
    __syncthreads();
    #pragma unroll
    for(int k=0;k<8;k++){
      int jj = lane + k*32;
      float4 p = tile[jj];
      float dot2 = __fmaf_rn(q.z, p.z, __fmaf_rn(q.y, p.y, __fmul_rn(q.x, p.x)));
      float d2   = __fsub_rn(__fadd_rn(q.w, p.w), dot2);
      unsigned mask = __ballot_sync(0xffffffffu, d2 <= bv[8]);
      while(mask){                      // uniform across warp
        int b = __ffs(mask)-1; mask &= mask-1;
        float v = __shfl_sync(0xffffffffu, d2, b);
        int  id = jt + b + k*32;
        if(v < bv[8] || (v==bv[8] && id < bi[8]))
          topk_insert(bv, bi, v, id);
      }
    }
  }
  if(lane==0){
    #pragma unroll
    for(int r=0;r<8;r++) g_nbr[i*NEI+r] = bi[1+r];   // drop slot 0 (self)
  }
}

// ---------------- edge geometry (sh2) + in-degree histogram -----------------
__global__ void k_edgegeo(const float* __restrict__ pos){
  int e=blockIdx.x*blockDim.x+threadIdx.x;
  if(e>=NE) return;
  int s=e>>3; int d=g_nbr[e];
  float ex=pos[d*3+0]-pos[s*3+0];
  float ey=pos[d*3+1]-pos[s*3+1];
  float ez=pos[d*3+2]-pos[s*3+2];
  float nrm = sqrtf(ex*ex+ey*ey+ez*ez) + 1e-12f;
  float x=ex/nrm, y=ey/nrm, z=ez/nrm;
  const float s15 = 3.8729833462074170f;  // sqrt(15)
  const float s5  = 2.2360679774997896f;  // sqrt(5)
  g_sh2[e*5+0] = s15*x*y;
  g_sh2[e*5+1] = s15*y*z;
  g_sh2[e*5+2] = 0.5f*s5*(3.f*z*z-1.f);
  g_sh2[e*5+3] = s15*x*z;
  g_sh2[e*5+4] = 0.5f*s15*(x*x-y*y);
  atomicAdd(&g_cnt[d],1);
}

// ---------------- exclusive scan (1 block) ----------------------------------
__global__ void k_scan(){
  __shared__ int tsum[1024];
  int t=threadIdx.x;
  int base=t*8; int local[8]; int s=0;
  #pragma unroll
  for(int k=0;k<8;k++){ local[k]=s; s+=g_cnt[base+k]; }
  tsum[t]=s; __syncthreads();
  for(int off=1; off<1024; off<<=1){
    int v = (t>=off)? tsum[t-off] : 0;
    __syncthreads();
    tsum[t]+=v;
    __syncthreads();
  }
  int prev = (t==0)?0:tsum[t-1];
  #pragma unroll
  for(int k=0;k<8;k++){ int val=prev+local[k]; g_rowptr[base+k]=val; g_cursor[base+k]=val; }
  if(t==1023) g_rowptr[NN]=tsum[1023];
}

__global__ void k_scatter(){
  int e=blockIdx.x*blockDim.x+threadIdx.x;
  if(e>=NE) return;
  int d=g_nbr[e];
  int p=atomicAdd(&g_cursor[d],1);
  g_csr[p]=e;
}

// sort each CSR row ascending -> deterministic aggregation order
__global__ void k_sortrows(){
  int n=blockIdx.x*blockDim.x+threadIdx.x;
  if(n>=NN) return;
  int b=g_rowptr[n], e2=g_rowptr[n+1];
  for(int i=b+1;i<e2;i++){
    int v=g_csr[i]; int j=i-1;
    while(j>=b && g_csr[j]>v){ g_csr[j+1]=g_csr[j]; j--; }
    g_csr[j+1]=v;
  }
}

__device__ __forceinline__ float load_edge_val(int t, int e){
  int s=e>>3;
  if(t<32)  return g_x0[s*32+t];
  if(t<80)  return g_x1[s*48+(t-32)];
  if(t<120) return g_x2[s*40+(t-80)];
  if(t<125) return g_sh2[e*5+(t-120)];
  return 0.f;
}

// ---------------- aggregate + linear: u-blocked, path-uniform warps ----------
// Block = 1 dst node, 160 threads = 5 warps:
//  w0: p1 (u=lane)            w1: p2 (u=lane, 5 o)
//  w2: p3 (lanes<16) / p4     w3: x2 quad p6/p7/p8/p9 (8 lanes each, padded 5x5)
//  w4: p5 (lanes<16)
// tp_w and K-direct tables hoisted out of the edge loop.
__global__ void __launch_bounds__(160) k_aggregate(int l, const float* __restrict__ tp_w,
                            const float* __restrict__ W0g,
                            const float* __restrict__ W1g,
                            const float* __restrict__ W2g){
  int d=blockIdx.x; int t=threadIdx.x;
  int warp=t>>5, lane=t&31;
  __shared__ float sK[405];
  __shared__ float sw[144];
  __shared__ float xs[2][128];      // x0 32 | x1 48 | x2 40 | sh 5 @120
  __shared__ float tC2[2][5];       // p2: S[o]
  __shared__ float tC4[2][9];       // p4: S[m*3+i]
  __shared__ float tC5[2][15];      // p5: S[o*3+i]
  __shared__ float tCQ[2][4][25];   // quad: [buf][g][o*5+i]; g0=p6(K const),1=p7,2=p8,3=p9
  __shared__ float sa[480];
  for(int i=t;i<405;i+=160) sK[i]=g_K[i];
  for(int i=t;i<144;i+=160) sw[i]=tp_w[l*144+i];
  __syncthreads();
  // fill constant table (p6) in both buffers + zero padding rows (p7 rows1-4, p8 rows3-4)
  if(t<25){ float v=sK[155+t]; tCQ[0][0][t]=v; tCQ[1][0][t]=v; }
  else if(t<65){ int x=t-25; tCQ[x&1][1][5+(x>>1)]=0.f; }        // 2 bufs x 20
  else if(t<85){ int x=t-65; tCQ[x&1][2][15+(x>>1)]=0.f; }       // 2 bufs x 10
  int b=g_rowptr[d], deg=g_rowptr[d+1]-b;
  float acc0=0.f, acc1=0.f, acc2=0.f, acc3=0.f, acc4=0.f;
  float vpre=0.f;
  if(deg>0) vpre = load_edge_val(t, g_csr[b]);
  __syncthreads();
  for(int q=0;q<deg;q++){
    int buf=q&1;
    if(t<125) xs[buf][t]=vpre;
    __syncthreads();
    if(q+1<deg) vpre = load_edge_val(t, g_csr[b+q+1]);
    if(t<74){
      const float* sh=&xs[buf][120];
      int koff; float* dst;
      if(t<5){ koff=1+t*5; dst=&tC2[buf][t]; }
      else if(t<14){ int x=t-5;  koff=35+(x/3)*15+(x%3)*5;  dst=&tC4[buf][x]; }
      else if(t<29){ int x=t-14; koff=80+(x/3)*15+(x%3)*5;  dst=&tC5[buf][x]; }
      else if(t<34){ int x=t-29; koff=180+x*5;              dst=&tCQ[buf][1][x]; }
      else if(t<49){ int x=t-34; koff=205+(x/5)*25+(x%5)*5; dst=&tCQ[buf][2][x]; }
      else         { int x=t-49; koff=280+(x/5)*25+(x%5)*5; dst=&tCQ[buf][3][x]; }
      float r = sK[koff]*sh[0];
      r = __fmaf_rn(sK[koff+1], sh[1], r);
      r = __fmaf_rn(sK[koff+2], sh[2], r);
      r = __fmaf_rn(sK[koff+3], sh[3], r);
      r = __fmaf_rn(sK[koff+4], sh[4], r);
      *dst = r;
    }
    __syncthreads();
    if(warp==0){
      acc0 += xs[buf][lane];                                  // p1
    } else if(warp==1){                                       // p2
      float v=xs[buf][lane];
      acc0 = __fmaf_rn(v, tC2[buf][0], acc0);
      acc1 = __fmaf_rn(v, tC2[buf][1], acc1);
      acc2 = __fmaf_rn(v, tC2[buf][2], acc2);
      acc3 = __fmaf_rn(v, tC2[buf][3], acc3);
      acc4 = __fmaf_rn(v, tC2[buf][4], acc4);
    } else if(warp==2){                                       // p3 / p4
      int u=lane&15;
      const float* cf = (lane<16)? (sK+26) : tC4[buf];
      const float* x1=&xs[buf][32+u*3];
      float a0=x1[0], a1=x1[1], a2=x1[2];
      acc0 = __fmaf_rn(a2, cf[2], __fmaf_rn(a1, cf[1], __fmaf_rn(a0, cf[0], acc0)));
      acc1 = __fmaf_rn(a2, cf[5], __fmaf_rn(a1, cf[4], __fmaf_rn(a0, cf[3], acc1)));
      acc2 = __fmaf_rn(a2, cf[8], __fmaf_rn(a1, cf[7], __fmaf_rn(a0, cf[6], acc2)));
    } else if(warp==3){                                       // x2 quad
      int g=lane>>3, u=lane&7;
      const float* cf = tCQ[buf][g];
      const float* x2=&xs[buf][80+u*5];
      float b0=x2[0],b1=x2[1],b2=x2[2],b3=x2[3],b4=x2[4];
      acc0 = __fmaf_rn(b4,cf[4], __fmaf_rn(b3,cf[3], __fmaf_rn(b2,cf[2], __fmaf_rn(b1,cf[1], __fmaf_rn(b0,cf[0], acc0)))));
      acc1 = __fmaf_rn(b4,cf[9], __fmaf_rn(b3,cf[8], __fmaf_rn(b2,cf[7], __fmaf_rn(b1,cf[6], __fmaf_rn(b0,cf[5], acc1)))));
      acc2 = __fmaf_rn(b4,cf[14],__fmaf_rn(b3,cf[13],__fmaf_rn(b2,cf[12],__fmaf_rn(b1,cf[11],__fmaf_rn(b0,cf[10],acc2)))));
      acc3 = __fmaf_rn(b4,cf[19],__fmaf_rn(b3,cf[18],__fmaf_rn(b2,cf[17],__fmaf_rn(b1,cf[16],__fmaf_rn(b0,cf[15],acc3)))));
      acc4 = __fmaf_rn(b4,cf[24],__fmaf_rn(b3,cf[23],__fmaf_rn(b2,cf[22],__fmaf_rn(b1,cf[21],__fmaf_rn(b0,cf[20],acc4)))));
    } else if(lane<16){                                       // p5
      int u=lane;
      const float* cf = tC5[buf];
      const float* x1=&xs[buf][32+u*3];
      float a0=x1[0], a1=x1[1], a2=x1[2];
      acc0 = __fmaf_rn(a2, cf[2],  __fmaf_rn(a1, cf[1],  __fmaf_rn(a0, cf[0],  acc0)));
      acc1 = __fmaf_rn(a2, cf[5],  __fmaf_rn(a1, cf[4],  __fmaf_rn(a0, cf[3],  acc1)));
      acc2 = __fmaf_rn(a2, cf[8],  __fmaf_rn(a1, cf[7],  __fmaf_rn(a0, cf[6],  acc2)));
      acc3 = __fmaf_rn(a2, cf[11], __fmaf_rn(a1, cf[10], __fmaf_rn(a0, cf[9],  acc3)));
      acc4 = __fmaf_rn(a2, cf[14], __fmaf_rn(a1, cf[13], __fmaf_rn(a0, cf[12], acc4)));
    }
  }
  // write accumulators (apply hoisted tp_w) into sa
  if(warp==0){
    sa[lane] = acc0*sK[0]*sw[lane];                                          // p1
  } else if(warp==1){
    int u=lane; float w=sw[32+u];
    sa[160+u*5+0]=acc0*w; sa[160+u*5+1]=acc1*w; sa[160+u*5+2]=acc2*w;
    sa[160+u*5+3]=acc3*w; sa[160+u*5+4]=acc4*w;                              // p2
  } else if(warp==2){
    int u=lane&15;
    if(lane<16){ float w=sw[64+u];
      sa[40+u*3+0]=acc0*w; sa[40+u*3+1]=acc1*w; sa[40+u*3+2]=acc2*w;         // p3
    } else {     float w=sw[80+u];
      sa[40+(16+u)*3+0]=acc0*w; sa[40+(16+u)*3+1]=acc1*w; sa[40+(16+u)*3+2]=acc2*w; // p4
    }
  } else if(warp==3){
    int g=lane>>3, u=lane&7;
    if(g==0){ float w=sw[112+u]; int base=160+(48+u)*5;                      // p6
      sa[base]=acc0*w; sa[base+1]=acc1*w; sa[base+2]=acc2*w; sa[base+3]=acc3*w; sa[base+4]=acc4*w;
    } else if(g==1){ sa[32+u]=acc0*sw[120+u];                                // p7
    } else if(g==2){ float w=sw[128+u]; int base=40+(32+u)*3;                // p8
      sa[base]=acc0*w; sa[base+1]=acc1*w; sa[base+2]=acc2*w;
    } else { float w=sw[136+u]; int base=160+(56+u)*5;                       // p9
      sa[base]=acc0*w; sa[base+1]=acc1*w; sa[base+2]=acc2*w; sa[base+3]=acc3*w; sa[base+4]=acc4*w;
    }
  } else if(lane<16){
    int u=lane; float w=sw[96+u]; int base=160+(32+u)*5;                     // p5
    sa[base]=acc0*w; sa[base+1]=acc1*w; sa[base+2]=acc2*w; sa[base+3]=acc3*w; sa[base+4]=acc4*w;
  }
  __syncthreads();
  const float* W0=W0g+l*1280; const float* W1=W1g+l*640; const float* W2=W2g+l*512;
  const float inv40 = 0.15811388300841897f;  // 1/sqrt(40)
  if(t<32){
    float s=0.f;
    #pragma unroll
    for(int u=0;u<40;u++) s += sa[u]*__ldg(&W0[u*32+t]);
    g_y0[d*32+t] = s*inv40;
  } else if(t<80){
    int q2=t-32; int v2=q2/3, m=q2-3*v2; float s=0.f;
    #pragma unroll
    for(int u=0;u<40;u++) s += sa[40+u*3+m]*__ldg(&W1[u*16+v2]);
    g_y1[d*48+v2*3+m] = s*inv40;
  } else if(t<120){
    int q2=t-80; int v2=q2/5, o=q2-5*v2; float s=0.f;
    #pragma unroll
    for(int u=0;u<64;u++) s += sa[160+u*5+o]*__ldg(&W2[u*8+v2]);
    g_y2[d*40+v2*5+o] = s*0.125f;       // 1/sqrt(64)
  }
}

// ---------------- BN stats (deterministic, double accum) --------------------
__global__ void k_stats(int l, const float* __restrict__ bw0, const float* __restrict__ bb0,
                        const float* __restrict__ bw1, const float* __restrict__ bw2){
  int b=blockIdx.x, t=threadIdx.x;
  __shared__ double r1[256], r2[256];
  double s1=0.0, s2=0.0;
  if(b<32){
    int c=b;
    for(int n=t;n<NN;n+=256){ double v=g_y0[n*32+c]; s1+=v; s2+=v*v; }
  } else if(b<48){
    int c=b-32;
    for(int n=t;n<NN;n+=256){
      #pragma unroll
      for(int m=0;m<3;m++){ double v=g_y1[n*48+c*3+m]; s2+=v*v; }
    }
  } else {
    int c=b-48;
    for(int n=t;n<NN;n+=256){
      #pragma unroll
      for(int o=0;o<5;o++){ double v=g_y2[n*40+c*5+o]; s2+=v*v; }
    }
  }
  r1[t]=s1; r2[t]=s2; __syncthreads();
  for(int off=128; off>=1; off>>=1){
    if(t<off){ r1[t]+=r1[t+off]; r2[t]+=r2[t+off]; }
    __syncthreads();
  }
  if(t==0){
    if(b<32){
      int c=b;
      double mu=r1[0]/(double)NN;
      double var=r2[0]/(double)NN - mu*mu;
      float scale = bw0[l*32+c]/sqrtf((float)var + EPSV);
      g_scale0[c]=scale;
      g_shift0[c]=bb0[l*32+c]-(float)mu*scale;
    } else if(b<48){
      int c=b-32;
      float mean=(float)(r2[0]/(double)(NN*3));
      g_scale1[c]=bw1[l*16+c]/sqrtf(mean+EPSV);
    } else {
      int c=b-48;
      float mean=(float)(r2[0]/(double)(NN*5));
      g_scale2[c]=bw2[l*8+c]/sqrtf(mean+EPSV);
    }
  }
}

// ---------------- normalize + relu + residual -------------------------------
__global__ void k_update(){
  int t=blockIdx.x*blockDim.x+threadIdx.x;
  if(t>=NN*120) return;
  int n=t/120, r=t-n*120;
  if(r<32){
    int idx=n*32+r;
    float v=g_y0[idx]*g_scale0[r]+g_shift0[r];
    g_x0[idx]+=fmaxf(v,0.f);
  } else if(r<80){
    int q=r-32; int u=q/3; int idx=n*48+q;
    float v=g_y1[idx]*g_scale1[u];
    g_x1[idx]+=fmaxf(v,0.f);
  } else {
    int q=r-80; int u=q/5; int idx=n*40+q;
    float v=g_y2[idx]*g_scale2[u];
    g_x2[idx]+=fmaxf(v,0.f);
  }
}

// ---------------- head MLP ---------------------------------------------------
__global__ void k_head(const float* __restrict__ Wf1, const float* __restrict__ Wf2,
                       const float* __restrict__ bf2, const float* __restrict__ Wf3,
                       const float* __restrict__ bf3, float* __restrict__ out){
  __shared__ float sW1[1024], sW2[512], sb2[16], sW3[32], sb3[2];
  int t=threadIdx.x;
  for(int i=t;i<1024;i+=128) sW1[i]=Wf1[i];
  for(int i=t;i<512;i+=128)  sW2[i]=Wf2[i];
  if(t<16) sb2[t]=bf2[t];
  if(t<32) sW3[t]=Wf3[t];
  if(t<2)  sb3[t]=bf3[t];
  __syncthreads();
  int n=blockIdx.x*128+t;
  float xin[32];
  #pragma unroll
  for(int i=0;i<32;i++) xin[i]=g_x0[n*32+i];
  const float c1=0.1767766952966369f;  // 1/sqrt(32)
  float h1[32];
  #pragma unroll
  for(int j=0;j<32;j++){
    float s=0.f;
    #pragma unroll
    for(int i=0;i<32;i++) s += xin[i]*sW1[i*32+j];
    h1[j]=fmaxf(s*c1,0.f);
  }
  float h2[16];
  #pragma unroll
  for(int k=0;k<16;k++){
    float s=sb2[k];
    #pragma unroll
    for(int j=0;j<32;j++) s += h1[j]*sW2[j*16+k];
    h2[k]=fmaxf(s,0.f);
  }
  #pragma unroll
  for(int m=0;m<2;m++){
    float s=sb3[m];
    #pragma unroll
    for(int k=0;k<16;k++) s += h2[k]*sW3[k*2+m];
    out[n*2+m]=s;
  }
}

// ---------------- launch ------------------------------------------------------
extern "C" void kernel_launch(void* const* d_in, const int* in_sizes, int n_in,
                              void* d_out, int out_size){
  const float* pos    = (const float*)d_in[0];
  const float* W_emb  = (const float*)d_in[1];
  const float* tp_w   = (const float*)d_in[2];
  const float* lin_W0 = (const float*)d_in[3];
  const float* lin_W1 = (const float*)d_in[4];
  const float* lin_W2 = (const float*)d_in[5];
  const float* bn_w0  = (const float*)d_in[6];
  const float* bn_b0  = (const float*)d_in[7];
  const float* bn_w1  = (const float*)d_in[8];
  const float* bn_w2  = (const float*)d_in[9];
  const float* Wf1    = (const float*)d_in[10];
  const float* Wf2    = (const float*)d_in[11];
  const float* bf2    = (const float*)d_in[12];
  const float* Wf3    = (const float*)d_in[13];
  const float* bf3    = (const float*)d_in[14];
  float* out = (float*)d_out;

  k_initK<<<9,128>>>();
  k_prep<<<(NN*120+255)/256,256>>>(pos, W_emb);
  k_knn<<<NN/8,256>>>();
  k_edgegeo<<<NE/256,256>>>(pos);
  k_scan<<<1,1024>>>();
  k_scatter<<<NE/256,256>>>();
  k_sortrows<<<NN/256,256>>>();
  for(int l=0;l<3;l++){
    k_aggregate<<<NN,160>>>(l, tp_w, lin_W0, lin_W1, lin_W2);
    k_stats<<<56,256>>>(l, bn_w0, bn_b0, bn_w1, bn_w2);
    k_update<<<(NN*120+255)/256,256>>>();
  }
  k_head<<<NN/128,128>>>(Wf1, Wf2, bf2, Wf3, bf3, out);
}

// round 11
// speedup vs baseline: 1.1001x; 1.1001x over previous
#include <cuda_runtime.h>
#include <math.h>

#define NN 8192
#define NEI 8
#define NE (NN*NEI)
#define EPSV 1e-5f

// ---------------- scratch (static device memory; no runtime alloc) -------------
__device__ float4 g_posq[NN];    // (x, y, z, |p|^2) fp32 (query side)
__device__ float4 g_posq2[NN];   // (2x, 2y, 2z, |p|^2) fp32 (candidate side)
__device__ int    g_nbr[NE];
__device__ float  g_sh2[NE*5];
__device__ int    g_cnt[NN];
__device__ int    g_rowptr[NN+1];
__device__ int    g_cursor[NN];
__device__ int    g_csr[NE];
__device__ float  g_x0[NN*32];
__device__ float  g_x1[NN*48];
__device__ float  g_x2[NN*40];
__device__ float  g_y0[NN*32];
__device__ float  g_y1[NN*48];
__device__ float  g_y2[NN*40];
__device__ float  g_K[405];
__device__ float  g_scale0[32], g_shift0[32], g_scale1[16], g_scale2[8];

// K tensor layout offsets ([o][i][j] row-major per path)
// paths: (0,0,0)@0 sz1 | (0,2,2)@1 sz25 | (1,0,1)@26 sz9 | (1,2,1)@35 sz45 |
// (1,2,2)@80 sz75 | (2,0,2)@155 sz25 | (2,2,0)@180 sz25 | (2,2,1)@205 sz75 | (2,2,2)@280 sz125

// ---------------- K tensor init (fp32) -----------------------------------------
__device__ float ffact(int n){ float r=1.f; for(int i=2;i<=n;i++) r*=(float)i; return r; }

__device__ float cg_coef_f(int j1,int m1,int j2,int m2,int j3,int m3){
  if(m1+m2!=m3 || j3<abs(j1-j2) || j3>j1+j2) return 0.f;
  float pre = sqrtf((2.f*j3+1.f)*ffact(j3+j1-j2)*ffact(j3-j1+j2)*ffact(j1+j2-j3)/ffact(j1+j2+j3+1));
  pre *= sqrtf(ffact(j3+m3)*ffact(j3-m3)*ffact(j1-m1)*ffact(j1+m1)*ffact(j2-m2)*ffact(j2+m2));
  float s=0.f;
  for(int k=0;k<=j1+j2-j3;k++){
    int d0=k, d1=j1+j2-j3-k, d2=j1-m1-k, d3=j2+m2-k, d4=j3-j2+m1+k, d5=j3-j1-m2+k;
    if(d0<0||d1<0||d2<0||d3<0||d4<0||d5<0) continue;
    float den = ffact(d0)*ffact(d1)*ffact(d2)*ffact(d3)*ffact(d4)*ffact(d5);
    s += ((k&1)? -1.f:1.f)/den;
  }
  return pre*s;
}

__device__ void q_entry_f(int l,int r,int c,float* re,float* im){
  int a=r-l, b=c-l; *re=0.f; *im=0.f;
  if(a==0 && b==0){ *re=1.f; return; }
  if(abs(a)!=abs(b) || a==0 || b==0) return;
  int m=abs(a); float s=0.70710678118654752f; float sgn=(m&1)? -1.f:1.f;
  if(a==m && b==m)       *re = sgn*s;
  else if(a==m && b==-m) *re = s;
  else if(a==-m && b==m) *im = -sgn*s;
  else                   *im = s;
}

__global__ void k_initK(){
  const int L1[9]={0,0,1,1,1,2,2,2,2};
  const int L2[9]={0,2,0,2,2,0,2,2,2};
  const int L3[9]={0,2,1,1,2,2,0,1,2};
  const int OFF[9]={0,1,26,35,80,155,180,205,280};
  int p=blockIdx.x, t=threadIdx.x;
  int l1=L1[p], l2=L2[p], l3=L3[p];
  int d1=2*l1+1, d2=2*l2+1, d3=2*l3+1;
  int tot=d1*d2*d3;
  __shared__ float s_re[125], s_im[125];
  __shared__ int s_useim;
  float re=0.f, im=0.f;
  if(t<tot){
    int c=t/(d1*d2); int rem=t-(c*d1*d2); int a=rem/d2; int b=rem-a*d2;
    for(int C=0;C<d3;C++){
      float q3r,q3i; q_entry_f(l3,c,C,&q3r,&q3i); q3i=-q3i;  // conj
      if(q3r==0.f && q3i==0.f) continue;
      for(int A=0;A<d1;A++){
        float q1r,q1i; q_entry_f(l1,a,A,&q1r,&q1i);
        if(q1r==0.f && q1i==0.f) continue;
        for(int B=0;B<d2;B++){
          float q2r,q2i; q_entry_f(l2,b,B,&q2r,&q2i);
          if(q2r==0.f && q2i==0.f) continue;
          float cgv = cg_coef_f(l1,A-l1,l2,B-l2,l3,C-l3);
          if(cgv==0.f) continue;
          float xr=q3r*q1r-q3i*q1i, xi=q3r*q1i+q3i*q1r;
          float yr=xr*q2r-xi*q2i,  yi=xr*q2i+xi*q2r;
          re += yr*cgv; im += yi*cgv;
        }
      }
    }
    s_re[t]=re; s_im[t]=im;
  }
  __syncthreads();
  if(t==0){
    float mr=0.f, mi=0.f;
    for(int k=0;k<tot;k++){ mr=fmaxf(mr,fabsf(s_re[k])); mi=fmaxf(mi,fabsf(s_im[k])); }
    s_useim = (mi>mr)?1:0;
  }
  __syncthreads();
  if(t<tot) g_K[OFF[p]+t] = s_useim ? s_im[t] : s_re[t];
}

// ---------------- prep (posq + cnt + x init, fused) -------------------------
__global__ void k_prep(const float* __restrict__ pos, const float* __restrict__ W_emb){
  int t=blockIdx.x*blockDim.x+threadIdx.x;
  if(t<NN){
    float x=pos[t*3+0], y=pos[t*3+1], z=pos[t*3+2];
    float sq = __fadd_rn(__fadd_rn(__fmul_rn(x,x),__fmul_rn(y,y)),__fmul_rn(z,z));
    float4 q;  q.x=x;      q.y=y;      q.z=z;      q.w=sq;  g_posq[t]=q;
    float4 q2; q2.x=2.f*x; q2.y=2.f*y; q2.z=2.f*z; q2.w=sq; g_posq2[t]=q2;
    g_cnt[t]=0;
  }
  if(t < NN*32)       g_x0[t] = W_emb[t & 31];
  else if(t < NN*80)  g_x1[t-NN*32] = 0.f;
  else if(t < NN*120) g_x2[t-NN*80] = 0.f;
}

// ---------------- KNN: warp-cooperative replicated top-9 ---------------------
// d2 bit-pattern frozen (matches reference). Candidate coords pre-scaled by 2
// (exact), so the fmaf chain produces 2*dot bit-exactly.
__device__ __forceinline__ void topk_insert(float (&bv)[9], int (&bi)[9], float v, int j){
  float cv=v; int ci=j;
  #pragma unroll
  for(int k=0;k<9;k++){
    bool sw = (cv<bv[k]) || (cv==bv[k] && ci<bi[k]);
    float tv=bv[k]; int ti=bi[k];
    if(sw){ bv[k]=cv; bi[k]=ci; cv=tv; ci=ti; }
  }
}

__global__ void __launch_bounds__(256) k_knn(){
  int warp = threadIdx.x>>5, lane = threadIdx.x&31;
  int i = blockIdx.x*8 + warp;
  float4 q = g_posq[i];
  float bv[9]; int bi[9];
  #pragma unroll
  for(int k=0;k<9;k++){ bv[k]=INFINITY; bi[k]=0x7fffffff; }
  __shared__ float4 tile[256];
  for(int jt=0; jt<NN; jt+=256){
    __syncthreads();
    tile[threadIdx.x] = g_posq2[jt+threadIdx.x];
    __syncthreads();
    #pragma unroll
    for(int k=0;k<8;k++){
      int jj = lane + k*32;
      float4 p = tile[jj];
      float dot2 = __fmaf_rn(q.z, p.z, __fmaf_rn(q.y, p.y, __fmul_rn(q.x, p.x)));
      float d2   = __fsub_rn(__fadd_rn(q.w, p.w), dot2);
      unsigned mask = __ballot_sync(0xffffffffu, d2 <= bv[8]);
      while(mask){                      // uniform across warp
        int b = __ffs(mask)-1; mask &= mask-1;
        float v = __shfl_sync(0xffffffffu, d2, b);
        int  id = jt + b + k*32;
        if(v < bv[8] || (v==bv[8] && id < bi[8]))
          topk_insert(bv, bi, v, id);
      }
    }
  }
  if(lane==0){
    #pragma unroll
    for(int r=0;r<8;r++) g_nbr[i*NEI+r] = bi[1+r];   // drop slot 0 (self)
  }
}

// ---------------- edge geometry (sh2) + in-degree histogram -----------------
__global__ void k_edgegeo(const float* __restrict__ pos){
  int e=blockIdx.x*blockDim.x+threadIdx.x;
  if(e>=NE) return;
  int s=e>>3; int d=g_nbr[e];
  float ex=pos[d*3+0]-pos[s*3+0];
  float ey=pos[d*3+1]-pos[s*3+1];
  float ez=pos[d*3+2]-pos[s*3+2];
  float nrm = sqrtf(ex*ex+ey*ey+ez*ez) + 1e-12f;
  float x=ex/nrm, y=ey/nrm, z=ez/nrm;
  const float s15 = 3.8729833462074170f;  // sqrt(15)
  const float s5  = 2.2360679774997896f;  // sqrt(5)
  g_sh2[e*5+0] = s15*x*y;
  g_sh2[e*5+1] = s15*y*z;
  g_sh2[e*5+2] = 0.5f*s5*(3.f*z*z-1.f);
  g_sh2[e*5+3] = s15*x*z;
  g_sh2[e*5+4] = 0.5f*s15*(x*x-y*y);
  atomicAdd(&g_cnt[d],1);
}

// ---------------- exclusive scan (1 block) ----------------------------------
__global__ void k_scan(){
  __shared__ int tsum[1024];
  int t=threadIdx.x;
  int base=t*8; int local[8]; int s=0;
  #pragma unroll
  for(int k=0;k<8;k++){ local[k]=s; s+=g_cnt[base+k]; }
  tsum[t]=s; __syncthreads();
  for(int off=1; off<1024; off<<=1){
    int v = (t>=off)? tsum[t-off] : 0;
    __syncthreads();
    tsum[t]+=v;
    __syncthreads();
  }
  int prev = (t==0)?0:tsum[t-1];
  #pragma unroll
  for(int k=0;k<8;k++){ int val=prev+local[k]; g_rowptr[base+k]=val; g_cursor[base+k]=val; }
  if(t==1023) g_rowptr[NN]=tsum[1023];
}

__global__ void k_scatter(){
  int e=blockIdx.x*blockDim.x+threadIdx.x;
  if(e>=NE) return;
  int d=g_nbr[e];
  int p=atomicAdd(&g_cursor[d],1);
  g_csr[p]=e;
}

// sort each CSR row ascending -> deterministic aggregation order
__global__ void k_sortrows(){
  int n=blockIdx.x*blockDim.x+threadIdx.x;
  if(n>=NN) return;
  int b=g_rowptr[n], e2=g_rowptr[n+1];
  for(int i=b+1;i<e2;i++){
    int v=g_csr[i]; int j=i-1;
    while(j>=b && g_csr[j]>v){ g_csr[j+1]=g_csr[j]; j--; }
    g_csr[j+1]=v;
  }
}

// ---------------- factored S: S_oi = sum_j K[o][i][j]*sh[j] -----------------
// sS layout: p2S@0(5: o) | p4S@5(9: m*3+i) | p5S@14(15: o*3+i) | p7S@29(5: i)
//            | p8S@34(15: m*5+i) | p9S@49(25: o*5+i)   total 74
__device__ __forceinline__ float compute_S(int t, const float* sh, const float* sK){
  int off; 
  if(t<5)       off = 1   + t*5;                               // p2: o=t
  else if(t<14){ int x=t-5;  off = 35  + (x/3)*15 + (x%3)*5; } // p4
  else if(t<29){ int x=t-14; off = 80  + (x/3)*15 + (x%3)*5; } // p5
  else if(t<34) off = 180 + (t-29)*5;                           // p7: i
  else if(t<49){ int x=t-34; off = 205 + (x/5)*25 + (x%5)*5; } // p8
  else         { int x=t-49; off = 280 + (x/5)*25 + (x%5)*5; } // p9
  float r = sK[off]*sh[0];
  r = __fmaf_rn(sK[off+1], sh[1], r);
  r = __fmaf_rn(sK[off+2], sh[2], r);
  r = __fmaf_rn(sK[off+3], sh[3], r);
  r = __fmaf_rn(sK[off+4], sh[4], r);
  return r;
}

// ---------------- per-slot message value (factored) -------------------------
__device__ __forceinline__ float slot_val2(int s, const float* X, const float* S,
                                           const float* sK, const float* sw){
  const float* x0=X; const float* x1=X+32; const float* x2=X+80;
  if(s<40){
    if(s<32) return x0[s]*sK[0]*sw[s];                         // p1 (0,0,0)
    int u=s-32; float t=0.f;                                    // p7 (2,2,0)
    #pragma unroll
    for(int i=0;i<5;i++) t = __fmaf_rn(x2[u*5+i], S[29+i], t);
    return t*sw[120+u];
  } else if(s<160){
    int q=s-40; int u=q/3, m=q-3*u;
    if(u<16){                                                   // p3 (1,0,1)
      float t=0.f;
      #pragma unroll
      for(int i=0;i<3;i++) t = __fmaf_rn(x1[u*3+i], sK[26+m*3+i], t);
      return t*sw[64+u];
    }
    if(u<32){                                                   // p4 (1,2,1)
      int uu=u-16; float t=0.f;
      #pragma unroll
      for(int i=0;i<3;i++) t = __fmaf_rn(x1[uu*3+i], S[5+m*3+i], t);
      return t*sw[80+uu];
    }
    int uu=u-32; float t=0.f;                                   // p8 (2,2,1)
    #pragma unroll
    for(int i=0;i<5;i++) t = __fmaf_rn(x2[uu*5+i], S[34+m*5+i], t);
    return t*sw[128+uu];
  } else {
    int q=s-160; int u=q/5, o=q-5*u;
    if(u<32) return x0[u]*S[o]*sw[32+u];                        // p2 (0,2,2)
    if(u<48){                                                   // p5 (1,2,2)
      int uu=u-32; float t=0.f;
      #pragma unroll
      for(int i=0;i<3;i++) t = __fmaf_rn(x1[uu*3+i], S[14+o*3+i], t);
      return t*sw[96+uu];
    }
    if(u<56){                                                   // p6 (2,0,2)
      int uu=u-48; float t=0.f;
      #pragma unroll
      for(int i=0;i<5;i++) t = __fmaf_rn(x2[uu*5+i], sK[155+o*5+i], t);
      return t*sw[112+uu];
    }
    int uu=u-56; float t=0.f;                                   // p9 (2,2,2)
    #pragma unroll
    for(int i=0;i<5;i++) t = __fmaf_rn(x2[uu*5+i], S[49+o*5+i], t);
    return t*sw[136+uu];
  }
}

__device__ __forceinline__ float load_edge_val(int t, int e){
  int s=e>>3;
  if(t<32)  return g_x0[s*32+t];
  if(t<80)  return g_x1[s*48+(t-32)];
  if(t<120) return g_x2[s*40+(t-80)];
  if(t<125) return g_sh2[e*5+(t-120)];
  return 0.f;
}

// ---------------- aggregate + linear (block per dst node) -------------------
__global__ void k_aggregate(int l, const float* __restrict__ tp_w,
                            const float* __restrict__ W0g,
                            const float* __restrict__ W1g,
                            const float* __restrict__ W2g){
  int d=blockIdx.x; int t=threadIdx.x;
  __shared__ float sK[405];
  __shared__ float sw[144];
  __shared__ float xs[2][128];
  __shared__ float sS[2][80];
  __shared__ float sa[480];
  for(int i=t;i<405;i+=128) sK[i]=g_K[i];
  for(int i=t;i<144;i+=128) sw[i]=tp_w[l*144+i];
  float acc0=0.f, acc1=0.f, acc2=0.f, acc3=0.f;
  int b=g_rowptr[d], deg=g_rowptr[d+1]-b;
  float v = 0.f;
  if(deg>0) v = load_edge_val(t, g_csr[b]);
  __syncthreads();   // sK/sw ready
  for(int q=0;q<deg;q++){
    int buf=q&1;
    if(t<125) xs[buf][t]=v;
    __syncthreads();                                    // xs[buf] ready
    if(q+1<deg) v = load_edge_val(t, g_csr[b+q+1]);     // prefetch (overlaps)
    if(t<74) sS[buf][t] = compute_S(t, &xs[buf][120], sK);
    __syncthreads();                                    // sS[buf] ready
    const float* X=xs[buf]; const float* S=sS[buf];
    acc0 += slot_val2(t,     X, S, sK, sw);
    acc1 += slot_val2(t+128, X, S, sK, sw);
    acc2 += slot_val2(t+256, X, S, sK, sw);
    if(t<96) acc3 += slot_val2(t+384, X, S, sK, sw);
  }
  __syncthreads();
  sa[t]=acc0; sa[t+128]=acc1; sa[t+256]=acc2; if(t<96) sa[t+384]=acc3;
  __syncthreads();
  const float* W0=W0g+l*1280; const float* W1=W1g+l*640; const float* W2=W2g+l*512;
  const float inv40 = 0.15811388300841897f;  // 1/sqrt(40)
  if(t<32){
    float s=0.f;
    #pragma unroll
    for(int u=0;u<40;u++) s += sa[u]*__ldg(&W0[u*32+t]);
    g_y0[d*32+t] = s*inv40;
  } else if(t<80){
    int q2=t-32; int v2=q2/3, m=q2-3*v2; float s=0.f;
    #pragma unroll
    for(int u=0;u<40;u++) s += sa[40+u*3+m]*__ldg(&W1[u*16+v2]);
    g_y1[d*48+v2*3+m] = s*inv40;
  } else if(t<120){
    int q2=t-80; int v2=q2/5, o=q2-5*v2; float s=0.f;
    #pragma unroll
    for(int u=0;u<64;u++) s += sa[160+u*5+o]*__ldg(&W2[u*8+v2]);
    g_y2[d*40+v2*5+o] = s*0.125f;       // 1/sqrt(64)
  }
}

// ---------------- BN stats (fp32 Kahan, deterministic) -----------------------
__global__ void k_stats(int l, const float* __restrict__ bw0, const float* __restrict__ bb0,
                        const float* __restrict__ bw1, const float* __restrict__ bw2){
  int b=blockIdx.x, t=threadIdx.x;
  __shared__ float r1[256], r2[256];
  float s1=0.f, c1=0.f, s2=0.f, c2=0.f;   // Kahan accumulators
  #define KADD1(x) { float yy=(x)-c1; float tt=s1+yy; c1=(tt-s1)-yy; s1=tt; }
  #define KADD2(x) { float yy=(x)-c2; float tt=s2+yy; c2=(tt-s2)-yy; s2=tt; }
  if(b<32){
    int c=b;
    for(int n=t;n<NN;n+=256){ float v=g_y0[n*32+c]; KADD1(v); KADD2(v*v); }
  } else if(b<48){
    int c=b-32;
    for(int n=t;n<NN;n+=256){
      #pragma unroll
      for(int m=0;m<3;m++){ float v=g_y1[n*48+c*3+m]; KADD2(v*v); }
    }
  } else {
    int c=b-48;
    for(int n=t;n<NN;n+=256){
      #pragma unroll
      for(int o=0;o<5;o++){ float v=g_y2[n*40+c*5+o]; KADD2(v*v); }
    }
  }
  #undef KADD1
  #undef KADD2
  r1[t]=s1; r2[t]=s2; __syncthreads();
  for(int off=128; off>=1; off>>=1){
    if(t<off){ r1[t]+=r1[t+off]; r2[t]+=r2[t+off]; }
    __syncthreads();
  }
  if(t==0){
    if(b<32){
      int c=b;
      float mu=r1[0]/(float)NN;
      float var=r2[0]/(float)NN - mu*mu;
      float scale = bw0[l*32+c]/sqrtf(var + EPSV);
      g_scale0[c]=scale;
      g_shift0[c]=bb0[l*32+c]-mu*scale;
    } else if(b<48){
      int c=b-32;
      float mean=r2[0]/(float)(NN*3);
      g_scale1[c]=bw1[l*16+c]/sqrtf(mean+EPSV);
    } else {
      int c=b-48;
      float mean=r2[0]/(float)(NN*5);
      g_scale2[c]=bw2[l*8+c]/sqrtf(mean+EPSV);
    }
  }
}

// ---------------- normalize + relu + residual -------------------------------
__global__ void k_update(){
  int t=blockIdx.x*blockDim.x+threadIdx.x;
  if(t>=NN*120) return;
  int n=t/120, r=t-n*120;
  if(r<32){
    int idx=n*32+r;
    float v=g_y0[idx]*g_scale0[r]+g_shift0[r];
    g_x0[idx]+=fmaxf(v,0.f);
  } else if(r<80){
    int q=r-32; int u=q/3; int idx=n*48+q;
    float v=g_y1[idx]*g_scale1[u];
    g_x1[idx]+=fmaxf(v,0.f);
  } else {
    int q=r-80; int u=q/5; int idx=n*40+q;
    float v=g_y2[idx]*g_scale2[u];
    g_x2[idx]+=fmaxf(v,0.f);
  }
}

// ---------------- head MLP ---------------------------------------------------
__global__ void k_head(const float* __restrict__ Wf1, const float* __restrict__ Wf2,
                       const float* __restrict__ bf2, const float* __restrict__ Wf3,
                       const float* __restrict__ bf3, float* __restrict__ out){
  __shared__ float sW1[1024], sW2[512], sb2[16], sW3[32], sb3[2];
  int t=threadIdx.x;
  for(int i=t;i<1024;i+=128) sW1[i]=Wf1[i];
  for(int i=t;i<512;i+=128)  sW2[i]=Wf2[i];
  if(t<16) sb2[t]=bf2[t];
  if(t<32) sW3[t]=Wf3[t];
  if(t<2)  sb3[t]=bf3[t];
  __syncthreads();
  int n=blockIdx.x*128+t;
  float xin[32];
  #pragma unroll
  for(int i=0;i<32;i++) xin[i]=g_x0[n*32+i];
  const float c1=0.1767766952966369f;  // 1/sqrt(32)
  float h1[32];
  #pragma unroll
  for(int j=0;j<32;j++){
    float s=0.f;
    #pragma unroll
    for(int i=0;i<32;i++) s += xin[i]*sW1[i*32+j];
    h1[j]=fmaxf(s*c1,0.f);
  }
  float h2[16];
  #pragma unroll
  for(int k=0;k<16;k++){
    float s=sb2[k];
    #pragma unroll
    for(int j=0;j<32;j++) s += h1[j]*sW2[j*16+k];
    h2[k]=fmaxf(s,0.f);
  }
  #pragma unroll
  for(int m=0;m<2;m++){
    float s=sb3[m];
    #pragma unroll
    for(int k=0;k<16;k++) s += h2[k]*sW3[k*2+m];
    out[n*2+m]=s;
  }
}

// ---------------- launch ------------------------------------------------------
extern "C" void kernel_launch(void* const* d_in, const int* in_sizes, int n_in,
                              void* d_out, int out_size){
  const float* pos    = (const float*)d_in[0];
  const float* W_emb  = (const float*)d_in[1];
  const float* tp_w   = (const float*)d_in[2];
  const float* lin_W0 = (const float*)d_in[3];
  const float* lin_W1 = (const float*)d_in[4];
  const float* lin_W2 = (const float*)d_in[5];
  const float* bn_w0  = (const float*)d_in[6];
  const float* bn_b0  = (const float*)d_in[7];
  const float* bn_w1  = (const float*)d_in[8];
  const float* bn_w2  = (const float*)d_in[9];
  const float* Wf1    = (const float*)d_in[10];
  const float* Wf2    = (const float*)d_in[11];
  const float* bf2    = (const float*)d_in[12];
  const float* Wf3    = (const float*)d_in[13];
  const float* bf3    = (const float*)d_in[14];
  float* out = (float*)d_out;

  k_initK<<<9,128>>>();
  k_prep<<<(NN*120+255)/256,256>>>(pos, W_emb);
  k_knn<<<NN/8,256>>>();
  k_edgegeo<<<NE/256,256>>>(pos);
  k_scan<<<1,1024>>>();
  k_scatter<<<NE/256,256>>>();
  k_sortrows<<<NN/256,256>>>();
  for(int l=0;l<3;l++){
    k_aggregate<<<NN,128>>>(l, tp_w, lin_W0, lin_W1, lin_W2);
    k_stats<<<56,256>>>(l, bn_w0, bn_b0, bn_w1, bn_w2);
    k_update<<<(NN*120+255)/256,256>>>();
  }
  k_head<<<NN/128,128>>>(Wf1, Wf2, bf2, Wf3, bf3, out);
}

// round 12
// speedup vs baseline: 1.1732x; 1.0664x over previous
#include <cuda_runtime.h>
#include <math.h>

#define NN 8192
#define NEI 8
#define NE (NN*NEI)
#define EPSV 1e-5f
#define MAXDEG 64

// ---------------- scratch (static device memory; no runtime alloc) -------------
__device__ float4 g_posq[NN];    // (x, y, z, |p|^2) fp32 (query side)
__device__ float4 g_posq2[NN];   // (2x, 2y, 2z, |p|^2) fp32 (candidate side)
__device__ int    g_nbr[NE];
__device__ float  g_sh2[NE*5];
__device__ int    g_cnt[NN];
__device__ int    g_row[NN*MAXDEG];
__device__ float  g_x0[NN*32];
__device__ float  g_x1[NN*48];
__device__ float  g_x2[NN*40];
__device__ float  g_y0[NN*32];
__device__ float  g_y1[NN*48];
__device__ float  g_y2[NN*40];
__device__ float  g_K[405];
__device__ float  g_scale0[32], g_shift0[32], g_scale1[16], g_scale2[8];

__constant__ float c_FACT[8] = {1.f,1.f,2.f,6.f,24.f,120.f,720.f,5040.f};

// K tensor layout offsets ([o][i][j] row-major per path)
// paths: (0,0,0)@0 sz1 | (0,2,2)@1 sz25 | (1,0,1)@26 sz9 | (1,2,1)@35 sz45 |
// (1,2,2)@80 sz75 | (2,0,2)@155 sz25 | (2,2,0)@180 sz25 | (2,2,1)@205 sz75 | (2,2,2)@280 sz125

// ---------------- K tensor math (fp32, factorial table) -------------------------
__device__ __forceinline__ float cg_coef_f(int j1,int m1,int j2,int m2,int j3,int m3){
  if(m1+m2!=m3 || j3<abs(j1-j2) || j3>j1+j2) return 0.f;
  float pre = sqrtf((2.f*j3+1.f)*c_FACT[j3+j1-j2]*c_FACT[j3-j1+j2]*c_FACT[j1+j2-j3]/c_FACT[j1+j2+j3+1]);
  pre *= sqrtf(c_FACT[j3+m3]*c_FACT[j3-m3]*c_FACT[j1-m1]*c_FACT[j1+m1]*c_FACT[j2-m2]*c_FACT[j2+m2]);
  float s=0.f;
  for(int k=0;k<=j1+j2-j3;k++){
    int d0=k, d1=j1+j2-j3-k, d2=j1-m1-k, d3=j2+m2-k, d4=j3-j2+m1+k, d5=j3-j1-m2+k;
    if(d0<0||d1<0||d2<0||d3<0||d4<0||d5<0) continue;
    float den = c_FACT[d0]*c_FACT[d1]*c_FACT[d2]*c_FACT[d3]*c_FACT[d4]*c_FACT[d5];
    s += ((k&1)? -1.f:1.f)/den;
  }
  return pre*s;
}

__device__ __forceinline__ void q_entry_f(int l,int r,int c,float* re,float* im){
  int a=r-l, b=c-l; *re=0.f; *im=0.f;
  if(a==0 && b==0){ *re=1.f; return; }
  if(abs(a)!=abs(b) || a==0 || b==0) return;
  int m=abs(a); float s=0.70710678118654752f; float sgn=(m&1)? -1.f:1.f;
  if(a==m && b==m)       *re = sgn*s;
  else if(a==m && b==-m) *re = s;
  else if(a==-m && b==m) *im = -sgn*s;
  else                   *im = s;
}

__device__ void initK_block(int p, int t){
  const int L1[9]={0,0,1,1,1,2,2,2,2};
  const int L2[9]={0,2,0,2,2,0,2,2,2};
  const int L3[9]={0,2,1,1,2,2,0,1,2};
  const int OFF[9]={0,1,26,35,80,155,180,205,280};
  int l1=L1[p], l2=L2[p], l3=L3[p];
  int d1=2*l1+1, d2=2*l2+1, d3=2*l3+1;
  int tot=d1*d2*d3;
  __shared__ float s_re[125], s_im[125];
  __shared__ int s_useim;
  float re=0.f, im=0.f;
  if(t<tot){
    int c=t/(d1*d2); int rem=t-(c*d1*d2); int a=rem/d2; int b=rem-a*d2;
    for(int C=0;C<d3;C++){
      float q3r,q3i; q_entry_f(l3,c,C,&q3r,&q3i); q3i=-q3i;  // conj
      if(q3r==0.f && q3i==0.f) continue;
      for(int A=0;A<d1;A++){
        float q1r,q1i; q_entry_f(l1,a,A,&q1r,&q1i);
        if(q1r==0.f && q1i==0.f) continue;
        for(int B=0;B<d2;B++){
          float q2r,q2i; q_entry_f(l2,b,B,&q2r,&q2i);
          if(q2r==0.f && q2i==0.f) continue;
          float cgv = cg_coef_f(l1,A-l1,l2,B-l2,l3,C-l3);
          if(cgv==0.f) continue;
          float xr=q3r*q1r-q3i*q1i, xi=q3r*q1i+q3i*q1r;
          float yr=xr*q2r-xi*q2i,  yi=xr*q2i+xi*q2r;
          re += yr*cgv; im += yi*cgv;
        }
      }
    }
    s_re[t]=re; s_im[t]=im;
  }
  __syncthreads();
  if(t==0){
    float mr=0.f, mi=0.f;
    for(int k=0;k<tot;k++){ mr=fmaxf(mr,fabsf(s_re[k])); mi=fmaxf(mi,fabsf(s_im[k])); }
    s_useim = (mi>mr)?1:0;
  }
  __syncthreads();
  if(t<tot) g_K[OFF[p]+t] = s_useim ? s_im[t] : s_re[t];
}

// ---------------- prep (posq + cnt + x init + K init, fused) -----------------
__global__ void k_prep(const float* __restrict__ pos, const float* __restrict__ W_emb){
  int t=blockIdx.x*blockDim.x+threadIdx.x;
  if(t<NN){
    float x=pos[t*3+0], y=pos[t*3+1], z=pos[t*3+2];
    float sq = __fadd_rn(__fadd_rn(__fmul_rn(x,x),__fmul_rn(y,y)),__fmul_rn(z,z));
    float4 q;  q.x=x;      q.y=y;      q.z=z;      q.w=sq;  g_posq[t]=q;
    float4 q2; q2.x=2.f*x; q2.y=2.f*y; q2.z=2.f*z; q2.w=sq; g_posq2[t]=q2;
    g_cnt[t]=0;
  }
  if(t < NN*32)       g_x0[t] = W_emb[t & 31];
  else if(t < NN*80)  g_x1[t-NN*32] = 0.f;
  else if(t < NN*120) g_x2[t-NN*80] = 0.f;
  if(blockIdx.x < 9) initK_block(blockIdx.x, threadIdx.x);
}

// ---------------- KNN: warp-cooperative replicated top-9 ---------------------
// d2 bit-pattern frozen (matches reference). Candidate coords pre-scaled by 2
// (exact), so the fmaf chain produces 2*dot bit-exactly.
__device__ __forceinline__ void topk_insert(float (&bv)[9], int (&bi)[9], float v, int j){
  float cv=v; int ci=j;
  #pragma unroll
  for(int k=0;k<9;k++){
    bool sw = (cv<bv[k]) || (cv==bv[k] && ci<bi[k]);
    float tv=bv[k]; int ti=bi[k];
    if(sw){ bv[k]=cv; bi[k]=ci; cv=tv; ci=ti; }
  }
}

__global__ void __launch_bounds__(256) k_knn(){
  int warp = threadIdx.x>>5, lane = threadIdx.x&31;
  int i = blockIdx.x*8 + warp;
  float4 q = g_posq[i];
  float bv[9]; int bi[9];
  #pragma unroll
  for(int k=0;k<9;k++){ bv[k]=INFINITY; bi[k]=0x7fffffff; }
  __shared__ float4 tile[256];
  for(int jt=0; jt<NN; jt+=256){
    __syncthreads();
    tile[threadIdx.x] = g_posq2[jt+threadIdx.x];
    __syncthreads();
    #pragma unroll
    for(int k=0;k<8;k++){
      int jj = lane + k*32;
      float4 p = tile[jj];
      float dot2 = __fmaf_rn(q.z, p.z, __fmaf_rn(q.y, p.y, __fmul_rn(q.x, p.x)));
      float d2   = __fsub_rn(__fadd_rn(q.w, p.w), dot2);
      unsigned mask = __ballot_sync(0xffffffffu, d2 <= bv[8]);
      while(mask){                      // uniform across warp
        int b = __ffs(mask)-1; mask &= mask-1;
        float v = __shfl_sync(0xffffffffu, d2, b);
        int  id = jt + b + k*32;
        if(v < bv[8] || (v==bv[8] && id < bi[8]))
          topk_insert(bv, bi, v, id);
      }
    }
  }
  if(lane==0){
    #pragma unroll
    for(int r=0;r<8;r++) g_nbr[i*NEI+r] = bi[1+r];   // drop slot 0 (self)
  }
}

// ---------------- edge geometry (sh2) + fixed-capacity row push --------------
__global__ void k_edgegeo(const float* __restrict__ pos){
  int e=blockIdx.x*blockDim.x+threadIdx.x;
  if(e>=NE) return;
  int s=e>>3; int d=g_nbr[e];
  float ex=pos[d*3+0]-pos[s*3+0];
  float ey=pos[d*3+1]-pos[s*3+1];
  float ez=pos[d*3+2]-pos[s*3+2];
  float nrm = sqrtf(ex*ex+ey*ey+ez*ez) + 1e-12f;
  float x=ex/nrm, y=ey/nrm, z=ez/nrm;
  const float s15 = 3.8729833462074170f;  // sqrt(15)
  const float s5  = 2.2360679774997896f;  // sqrt(5)
  g_sh2[e*5+0] = s15*x*y;
  g_sh2[e*5+1] = s15*y*z;
  g_sh2[e*5+2] = 0.5f*s5*(3.f*z*z-1.f);
  g_sh2[e*5+3] = s15*x*z;
  g_sh2[e*5+4] = 0.5f*s15*(x*x-y*y);
  int slot = atomicAdd(&g_cnt[d],1);
  if(slot < MAXDEG) g_row[d*MAXDEG+slot] = e;
}

// ---------------- factored S: S_oi = sum_j K[o][i][j]*sh[j] -----------------
// sS layout: p2S@0(5: o) | p4S@5(9: m*3+i) | p5S@14(15: o*3+i) | p7S@29(5: i)
//            | p8S@34(15: m*5+i) | p9S@49(25: o*5+i)   total 74
__device__ __forceinline__ float compute_S(int t, const float* sh, const float* sK){
  int off; 
  if(t<5)       off = 1   + t*5;                               // p2: o=t
  else if(t<14){ int x=t-5;  off = 35  + (x/3)*15 + (x%3)*5; } // p4
  else if(t<29){ int x=t-14; off = 80  + (x/3)*15 + (x%3)*5; } // p5
  else if(t<34) off = 180 + (t-29)*5;                           // p7: i
  else if(t<49){ int x=t-34; off = 205 + (x/5)*25 + (x%5)*5; } // p8
  else         { int x=t-49; off = 280 + (x/5)*25 + (x%5)*5; } // p9
  float r = sK[off]*sh[0];
  r = __fmaf_rn(sK[off+1], sh[1], r);
  r = __fmaf_rn(sK[off+2], sh[2], r);
  r = __fmaf_rn(sK[off+3], sh[3], r);
  r = __fmaf_rn(sK[off+4], sh[4], r);
  return r;
}

// ---------------- per-slot message value (factored) -------------------------
__device__ __forceinline__ float slot_val2(int s, const float* X, const float* S,
                                           const float* sK, const float* sw){
  const float* x0=X; const float* x1=X+32; const float* x2=X+80;
  if(s<40){
    if(s<32) return x0[s]*sK[0]*sw[s];                         // p1 (0,0,0)
    int u=s-32; float t=0.f;                                    // p7 (2,2,0)
    #pragma unroll
    for(int i=0;i<5;i++) t = __fmaf_rn(x2[u*5+i], S[29+i], t);
    return t*sw[120+u];
  } else if(s<160){
    int q=s-40; int u=q/3, m=q-3*u;
    if(u<16){                                                   // p3 (1,0,1)
      float t=0.f;
      #pragma unroll
      for(int i=0;i<3;i++) t = __fmaf_rn(x1[u*3+i], sK[26+m*3+i], t);
      return t*sw[64+u];
    }
    if(u<32){                                                   // p4 (1,2,1)
      int uu=u-16; float t=0.f;
      #pragma unroll
      for(int i=0;i<3;i++) t = __fmaf_rn(x1[uu*3+i], S[5+m*3+i], t);
      return t*sw[80+uu];
    }
    int uu=u-32; float t=0.f;                                   // p8 (2,2,1)
    #pragma unroll
    for(int i=0;i<5;i++) t = __fmaf_rn(x2[uu*5+i], S[34+m*5+i], t);
    return t*sw[128+uu];
  } else {
    int q=s-160; int u=q/5, o=q-5*u;
    if(u<32) return x0[u]*S[o]*sw[32+u];                        // p2 (0,2,2)
    if(u<48){                                                   // p5 (1,2,2)
      int uu=u-32; float t=0.f;
      #pragma unroll
      for(int i=0;i<3;i++) t = __fmaf_rn(x1[uu*3+i], S[14+o*3+i], t);
      return t*sw[96+uu];
    }
    if(u<56){                                                   // p6 (2,0,2)
      int uu=u-48; float t=0.f;
      #pragma unroll
      for(int i=0;i<5;i++) t = __fmaf_rn(x2[uu*5+i], sK[155+o*5+i], t);
      return t*sw[112+uu];
    }
    int uu=u-56; float t=0.f;                                   // p9 (2,2,2)
    #pragma unroll
    for(int i=0;i<5;i++) t = __fmaf_rn(x2[uu*5+i], S[49+o*5+i], t);
    return t*sw[136+uu];
  }
}

__device__ __forceinline__ float load_edge_val(int t, int e){
  int s=e>>3;
  if(t<32)  return g_x0[s*32+t];
  if(t<80)  return g_x1[s*48+(t-32)];
  if(t<120) return g_x2[s*40+(t-80)];
  if(t<125) return g_sh2[e*5+(t-120)];
  return 0.f;
}

// ---------------- aggregate + linear (block per dst node) -------------------
// in-block sort of fixed-capacity row -> deterministic ascending edge order
__global__ void k_aggregate(int l, const float* __restrict__ tp_w,
                            const float* __restrict__ W0g,
                            const float* __restrict__ W1g,
                            const float* __restrict__ W2g){
  int d=blockIdx.x; int t=threadIdx.x;
  __shared__ float sK[405];
  __shared__ float sw[144];
  __shared__ float xs[2][128];
  __shared__ float sS[2][80];
  __shared__ float sa[480];
  __shared__ int   srow[MAXDEG];
  int deg = g_cnt[d]; if(deg>MAXDEG) deg=MAXDEG;
  if(t<deg) srow[t]=g_row[d*MAXDEG+t];
  for(int i=t;i<405;i+=128) sK[i]=g_K[i];
  for(int i=t;i<144;i+=128) sw[i]=tp_w[l*144+i];
  __syncthreads();
  if(t==0 && deg>1){                       // tiny insertion sort (avg deg ~8)
    for(int i=1;i<deg;i++){
      int v2=srow[i]; int j=i-1;
      while(j>=0 && srow[j]>v2){ srow[j+1]=srow[j]; j--; }
      srow[j+1]=v2;
    }
  }
  __syncthreads();
  float acc0=0.f, acc1=0.f, acc2=0.f, acc3=0.f;
  float v = 0.f;
  if(deg>0) v = load_edge_val(t, srow[0]);
  for(int q=0;q<deg;q++){
    int buf=q&1;
    if(t<125) xs[buf][t]=v;
    __syncthreads();                                    // xs[buf] ready
    if(q+1<deg) v = load_edge_val(t, srow[q+1]);        // prefetch (overlaps)
    if(t<74) sS[buf][t] = compute_S(t, &xs[buf][120], sK);
    __syncthreads();                                    // sS[buf] ready
    const float* X=xs[buf]; const float* S=sS[buf];
    acc0 += slot_val2(t,     X, S, sK, sw);
    acc1 += slot_val2(t+128, X, S, sK, sw);
    acc2 += slot_val2(t+256, X, S, sK, sw);
    if(t<96) acc3 += slot_val2(t+384, X, S, sK, sw);
  }
  __syncthreads();
  sa[t]=acc0; sa[t+128]=acc1; sa[t+256]=acc2; if(t<96) sa[t+384]=acc3;
  __syncthreads();
  const float* W0=W0g+l*1280; const float* W1=W1g+l*640; const float* W2=W2g+l*512;
  const float inv40 = 0.15811388300841897f;  // 1/sqrt(40)
  if(t<32){
    float s=0.f;
    #pragma unroll
    for(int u=0;u<40;u++) s += sa[u]*__ldg(&W0[u*32+t]);
    g_y0[d*32+t] = s*inv40;
  } else if(t<80){
    int q2=t-32; int v2=q2/3, m=q2-3*v2; float s=0.f;
    #pragma unroll
    for(int u=0;u<40;u++) s += sa[40+u*3+m]*__ldg(&W1[u*16+v2]);
    g_y1[d*48+v2*3+m] = s*inv40;
  } else if(t<120){
    int q2=t-80; int v2=q2/5, o=q2-5*v2; float s=0.f;
    #pragma unroll
    for(int u=0;u<64;u++) s += sa[160+u*5+o]*__ldg(&W2[u*8+v2]);
    g_y2[d*40+v2*5+o] = s*0.125f;       // 1/sqrt(64)
  }
}

// ---------------- BN stats (fp32 Kahan, deterministic) -----------------------
__global__ void k_stats(int l, const float* __restrict__ bw0, const float* __restrict__ bb0,
                        const float* __restrict__ bw1, const float* __restrict__ bw2){
  int b=blockIdx.x, t=threadIdx.x;
  __shared__ float r1[256], r2[256];
  float s1=0.f, c1=0.f, s2=0.f, c2=0.f;   // Kahan accumulators
  #define KADD1(x) { float yy=(x)-c1; float tt=s1+yy; c1=(tt-s1)-yy; s1=tt; }
  #define KADD2(x) { float yy=(x)-c2; float tt=s2+yy; c2=(tt-s2)-yy; s2=tt; }
  if(b<32){
    int c=b;
    for(int n=t;n<NN;n+=256){ float v=g_y0[n*32+c]; KADD1(v); KADD2(v*v); }
  } else if(b<48){
    int c=b-32;
    for(int n=t;n<NN;n+=256){
      #pragma unroll
      for(int m=0;m<3;m++){ float v=g_y1[n*48+c*3+m]; KADD2(v*v); }
    }
  } else {
    int c=b-48;
    for(int n=t;n<NN;n+=256){
      #pragma unroll
      for(int o=0;o<5;o++){ float v=g_y2[n*40+c*5+o]; KADD2(v*v); }
    }
  }
  #undef KADD1
  #undef KADD2
  r1[t]=s1; r2[t]=s2; __syncthreads();
  for(int off=128; off>=1; off>>=1){
    if(t<off){ r1[t]+=r1[t+off]; r2[t]+=r2[t+off]; }
    __syncthreads();
  }
  if(t==0){
    if(b<32){
      int c=b;
      float mu=r1[0]/(float)NN;
      float var=r2[0]/(float)NN - mu*mu;
      float scale = bw0[l*32+c]/sqrtf(var + EPSV);
      g_scale0[c]=scale;
      g_shift0[c]=bb0[l*32+c]-mu*scale;
    } else if(b<48){
      int c=b-32;
      float mean=r2[0]/(float)(NN*3);
      g_scale1[c]=bw1[l*16+c]/sqrtf(mean+EPSV);
    } else {
      int c=b-48;
      float mean=r2[0]/(float)(NN*5);
      g_scale2[c]=bw2[l*8+c]/sqrtf(mean+EPSV);
    }
  }
}

// ---------------- normalize + relu + residual -------------------------------
__global__ void k_update(){
  int t=blockIdx.x*blockDim.x+threadIdx.x;
  if(t>=NN*120) return;
  int n=t/120, r=t-n*120;
  if(r<32){
    int idx=n*32+r;
    float v=g_y0[idx]*g_scale0[r]+g_shift0[r];
    g_x0[idx]+=fmaxf(v,0.f);
  } else if(r<80){
    int q=r-32; int u=q/3; int idx=n*48+q;
    float v=g_y1[idx]*g_scale1[u];
    g_x1[idx]+=fmaxf(v,0.f);
  } else {
    int q=r-80; int u=q/5; int idx=n*40+q;
    float v=g_y2[idx]*g_scale2[u];
    g_x2[idx]+=fmaxf(v,0.f);
  }
}

// ---------------- head MLP ---------------------------------------------------
__global__ void k_head(const float* __restrict__ Wf1, const float* __restrict__ Wf2,
                       const float* __restrict__ bf2, const float* __restrict__ Wf3,
                       const float* __restrict__ bf3, float* __restrict__ out){
  __shared__ float sW1[1024], sW2[512], sb2[16], sW3[32], sb3[2];
  int t=threadIdx.x;
  for(int i=t;i<1024;i+=128) sW1[i]=Wf1[i];
  for(int i=t;i<512;i+=128)  sW2[i]=Wf2[i];
  if(t<16) sb2[t]=bf2[t];
  if(t<32) sW3[t]=Wf3[t];
  if(t<2)  sb3[t]=bf3[t];
  __syncthreads();
  int n=blockIdx.x*128+t;
  float xin[32];
  #pragma unroll
  for(int i=0;i<32;i++) xin[i]=g_x0[n*32+i];
  const float c1=0.1767766952966369f;  // 1/sqrt(32)
  float h1[32];
  #pragma unroll
  for(int j=0;j<32;j++){
    float s=0.f;
    #pragma unroll
    for(int i=0;i<32;i++) s += xin[i]*sW1[i*32+j];
    h1[j]=fmaxf(s*c1,0.f);
  }
  float h2[16];
  #pragma unroll
  for(int k=0;k<16;k++){
    float s=sb2[k];
    #pragma unroll
    for(int j=0;j<32;j++) s += h1[j]*sW2[j*16+k];
    h2[k]=fmaxf(s,0.f);
  }
  #pragma unroll
  for(int m=0;m<2;m++){
    float s=sb3[m];
    #pragma unroll
    for(int k=0;k<16;k++) s += h2[k]*sW3[k*2+m];
    out[n*2+m]=s;
  }
}

// ---------------- launch ------------------------------------------------------
extern "C" void kernel_launch(void* const* d_in, const int* in_sizes, int n_in,
                              void* d_out, int out_size){
  const float* pos    = (const float*)d_in[0];
  const float* W_emb  = (const float*)d_in[1];
  const float* tp_w   = (const float*)d_in[2];
  const float* lin_W0 = (const float*)d_in[3];
  const float* lin_W1 = (const float*)d_in[4];
  const float* lin_W2 = (const float*)d_in[5];
  const float* bn_w0  = (const float*)d_in[6];
  const float* bn_b0  = (const float*)d_in[7];
  const float* bn_w1  = (const float*)d_in[8];
  const float* bn_w2  = (const float*)d_in[9];
  const float* Wf1    = (const float*)d_in[10];
  const float* Wf2    = (const float*)d_in[11];
  const float* bf2    = (const float*)d_in[12];
  const float* Wf3    = (const float*)d_in[13];
  const float* bf3    = (const float*)d_in[14];
  float* out = (float*)d_out;

  k_prep<<<(NN*120+255)/256,256>>>(pos, W_emb);
  k_knn<<<NN/8,256>>>();
  k_edgegeo<<<NE/256,256>>>(pos);
  for(int l=0;l<3;l++){
    k_aggregate<<<NN,128>>>(l, tp_w, lin_W0, lin_W1, lin_W2);
    k_stats<<<56,256>>>(l, bn_w0, bn_b0, bn_w1, bn_w2);
    k_update<<<(NN*120+255)/256,256>>>();
  }
  k_head<<<NN/128,128>>>(Wf1, Wf2, bf2, Wf3, bf3, out);
}

// round 13
// speedup vs baseline: 1.3303x; 1.1340x over previous
#include <cuda_runtime.h>
#include <math.h>

#define NN 8192
#define NEI 8
#define NE (NN*NEI)
#define EPSV 1e-5f
#define MAXDEG 64

// ---------------- scratch (static device memory; no runtime alloc) -------------
__device__ float4 g_posq[NN];    // (x, y, z, |p|^2) fp32 (query side)
__device__ float4 g_posq2[NN];   // (2x, 2y, 2z, |p|^2) fp32 (candidate side)
__device__ int    g_nbr[NE];
__device__ float  g_sh2[NE*5];
__device__ int    g_cnt[NN];
__device__ int    g_row[NN*MAXDEG];
__device__ float  g_x0[NN*32];
__device__ float  g_x1[NN*48];
__device__ float  g_x2[NN*40];
__device__ float  g_y0[NN*32];
__device__ float  g_y1[NN*48];
__device__ float  g_y2[NN*40];
__device__ float  g_K[405];
__device__ float  g_scale0[32], g_shift0[32], g_scale1[16], g_scale2[8];

__constant__ float c_FACT[8] = {1.f,1.f,2.f,6.f,24.f,120.f,720.f,5040.f};

// K tensor layout offsets ([o][i][j] row-major per path)
// paths: (0,0,0)@0 sz1 | (0,2,2)@1 sz25 | (1,0,1)@26 sz9 | (1,2,1)@35 sz45 |
// (1,2,2)@80 sz75 | (2,0,2)@155 sz25 | (2,2,0)@180 sz25 | (2,2,1)@205 sz75 | (2,2,2)@280 sz125

// ---------------- K tensor math (fp32, factorial table) -------------------------
__device__ __forceinline__ float cg_coef_f(int j1,int m1,int j2,int m2,int j3,int m3){
  if(m1+m2!=m3 || j3<abs(j1-j2) || j3>j1+j2) return 0.f;
  float pre = sqrtf((2.f*j3+1.f)*c_FACT[j3+j1-j2]*c_FACT[j3-j1+j2]*c_FACT[j1+j2-j3]/c_FACT[j1+j2+j3+1]);
  pre *= sqrtf(c_FACT[j3+m3]*c_FACT[j3-m3]*c_FACT[j1-m1]*c_FACT[j1+m1]*c_FACT[j2-m2]*c_FACT[j2+m2]);
  float s=0.f;
  for(int k=0;k<=j1+j2-j3;k++){
    int d0=k, d1=j1+j2-j3-k, d2=j1-m1-k, d3=j2+m2-k, d4=j3-j2+m1+k, d5=j3-j1-m2+k;
    if(d0<0||d1<0||d2<0||d3<0||d4<0||d5<0) continue;
    float den = c_FACT[d0]*c_FACT[d1]*c_FACT[d2]*c_FACT[d3]*c_FACT[d4]*c_FACT[d5];
    s += ((k&1)? -1.f:1.f)/den;
  }
  return pre*s;
}

__device__ __forceinline__ void q_entry_f(int l,int r,int c,float* re,float* im){
  int a=r-l, b=c-l; *re=0.f; *im=0.f;
  if(a==0 && b==0){ *re=1.f; return; }
  if(abs(a)!=abs(b) || a==0 || b==0) return;
  int m=abs(a); float s=0.70710678118654752f; float sgn=(m&1)? -1.f:1.f;
  if(a==m && b==m)       *re = sgn*s;
  else if(a==m && b==-m) *re = s;
  else if(a==-m && b==m) *im = -sgn*s;
  else                   *im = s;
}

__device__ void initK_block(int p, int t){
  const int L1[9]={0,0,1,1,1,2,2,2,2};
  const int L2[9]={0,2,0,2,2,0,2,2,2};
  const int L3[9]={0,2,1,1,2,2,0,1,2};
  const int OFF[9]={0,1,26,35,80,155,180,205,280};
  int l1=L1[p], l2=L2[p], l3=L3[p];
  int d1=2*l1+1, d2=2*l2+1, d3=2*l3+1;
  int tot=d1*d2*d3;
  __shared__ float s_re[125], s_im[125];
  __shared__ int s_useim;
  float re=0.f, im=0.f;
  if(t<tot){
    int c=t/(d1*d2); int rem=t-(c*d1*d2); int a=rem/d2; int b=rem-a*d2;
    for(int C=0;C<d3;C++){
      float q3r,q3i; q_entry_f(l3,c,C,&q3r,&q3i); q3i=-q3i;  // conj
      if(q3r==0.f && q3i==0.f) continue;
      for(int A=0;A<d1;A++){
        float q1r,q1i; q_entry_f(l1,a,A,&q1r,&q1i);
        if(q1r==0.f && q1i==0.f) continue;
        for(int B=0;B<d2;B++){
          float q2r,q2i; q_entry_f(l2,b,B,&q2r,&q2i);
          if(q2r==0.f && q2i==0.f) continue;
          float cgv = cg_coef_f(l1,A-l1,l2,B-l2,l3,C-l3);
          if(cgv==0.f) continue;
          float xr=q3r*q1r-q3i*q1i, xi=q3r*q1i+q3i*q1r;
          float yr=xr*q2r-xi*q2i,  yi=xr*q2i+xi*q2r;
          re += yr*cgv; im += yi*cgv;
        }
      }
    }
    s_re[t]=re; s_im[t]=im;
  }
  __syncthreads();
  if(t==0){
    float mr=0.f, mi=0.f;
    for(int k=0;k<tot;k++){ mr=fmaxf(mr,fabsf(s_re[k])); mi=fmaxf(mi,fabsf(s_im[k])); }
    s_useim = (mi>mr)?1:0;
  }
  __syncthreads();
  if(t<tot) g_K[OFF[p]+t] = s_useim ? s_im[t] : s_re[t];
}

// ---------------- prep (posq + cnt + x init + K init, fused) -----------------
__global__ void k_prep(const float* __restrict__ pos, const float* __restrict__ W_emb){
  int t=blockIdx.x*blockDim.x+threadIdx.x;
  if(t<NN){
    float x=pos[t*3+0], y=pos[t*3+1], z=pos[t*3+2];
    float sq = __fadd_rn(__fadd_rn(__fmul_rn(x,x),__fmul_rn(y,y)),__fmul_rn(z,z));
    float4 q;  q.x=x;      q.y=y;      q.z=z;      q.w=sq;  g_posq[t]=q;
    float4 q2; q2.x=2.f*x; q2.y=2.f*y; q2.z=2.f*z; q2.w=sq; g_posq2[t]=q2;
    g_cnt[t]=0;
  }
  if(t < NN*32)       g_x0[t] = W_emb[t & 31];
  else if(t < NN*80)  g_x1[t-NN*32] = 0.f;
  else if(t < NN*120) g_x2[t-NN*80] = 0.f;
  if(blockIdx.x < 9) initK_block(blockIdx.x, threadIdx.x);
}

// ---------------- KNN: warp-cooperative replicated top-9 ---------------------
// d2 bit-pattern frozen (matches reference). Candidate coords pre-scaled by 2
// (exact), so the fmaf chain produces 2*dot bit-exactly.
__device__ __forceinline__ void topk_insert(float (&bv)[9], int (&bi)[9], float v, int j){
  float cv=v; int ci=j;
  #pragma unroll
  for(int k=0;k<9;k++){
    bool sw = (cv<bv[k]) || (cv==bv[k] && ci<bi[k]);
    float tv=bv[k]; int ti=bi[k];
    if(sw){ bv[k]=cv; bi[k]=ci; cv=tv; ci=ti; }
  }
}

__global__ void __launch_bounds__(256) k_knn(){
  int warp = threadIdx.x>>5, lane = threadIdx.x&31;
  int i = blockIdx.x*8 + warp;
  float4 q = g_posq[i];
  float bv[9]; int bi[9];
  #pragma unroll
  for(int k=0;k<9;k++){ bv[k]=INFINITY; bi[k]=0x7fffffff; }
  __shared__ float4 tile[256];
  for(int jt=0; jt<NN; jt+=256){
    __syncthreads();
    tile[threadIdx.x] = g_posq2[jt+threadIdx.x];
    __syncthreads();
    #pragma unroll
    for(int k=0;k<8;k++){
      int jj = lane + k*32;
      float4 p = tile[jj];
      float dot2 = __fmaf_rn(q.z, p.z, __fmaf_rn(q.y, p.y, __fmul_rn(q.x, p.x)));
      float d2   = __fsub_rn(__fadd_rn(q.w, p.w), dot2);
      unsigned mask = __ballot_sync(0xffffffffu, d2 <= bv[8]);
      while(mask){                      // uniform across warp
        int b = __ffs(mask)-1; mask &= mask-1;
        float v = __shfl_sync(0xffffffffu, d2, b);
        int  id = jt + b + k*32;
        if(v < bv[8] || (v==bv[8] && id < bi[8]))
          topk_insert(bv, bi, v, id);
      }
    }
  }
  if(lane==0){
    #pragma unroll
    for(int r=0;r<8;r++) g_nbr[i*NEI+r] = bi[1+r];   // drop slot 0 (self)
  }
}

// ---------------- edge geometry (sh2) + fixed-capacity row push --------------
__global__ void k_edgegeo(const float* __restrict__ pos){
  int e=blockIdx.x*blockDim.x+threadIdx.x;
  if(e>=NE) return;
  int s=e>>3; int d=g_nbr[e];
  float ex=pos[d*3+0]-pos[s*3+0];
  float ey=pos[d*3+1]-pos[s*3+1];
  float ez=pos[d*3+2]-pos[s*3+2];
  float nrm = sqrtf(ex*ex+ey*ey+ez*ez) + 1e-12f;
  float x=ex/nrm, y=ey/nrm, z=ez/nrm;
  const float s15 = 3.8729833462074170f;  // sqrt(15)
  const float s5  = 2.2360679774997896f;  // sqrt(5)
  g_sh2[e*5+0] = s15*x*y;
  g_sh2[e*5+1] = s15*y*z;
  g_sh2[e*5+2] = 0.5f*s5*(3.f*z*z-1.f);
  g_sh2[e*5+3] = s15*x*z;
  g_sh2[e*5+4] = 0.5f*s15*(x*x-y*y);
  int slot = atomicAdd(&g_cnt[d],1);
  if(slot < MAXDEG) g_row[d*MAXDEG+slot] = e;
}

__device__ __forceinline__ float load_edge_val(int t, int e){
  int s=e>>3;
  if(t<32)  return g_x0[s*32+t];
  if(t<80)  return g_x1[s*48+(t-32)];
  if(t<120) return g_x2[s*40+(t-80)];
  if(t<125) return g_sh2[e*5+(t-120)];
  return 0.f;
}

// ---------------- aggregate + linear: warp-uniform register-blocked ----------
// Block = 1 dst node, 128 threads = 4 warps, one thread per (path,u) row:
//  W0: p1+p2 (u=lane, x0)                    6 FMA
//  W1: lanes<16 p3 (coef=K) / p4 (coef=S)    3x3 uniform
//  W2: p5 split-o (u=lane>>1, half=lane&1)   3x3 uniform
//  W3: g=lane>>3: p6(K)/p7/p8/p9 padded 5x5  25 FMA uniform (zero-pad exact)
// S table layout (per buffer, 124 slots, pads stay zero):
//  p2S@0(5) | p4S@8(9) | p5S@20(18: o*3+i, slots 15-17 pad) |
//  p7S@48(25: row o=0 real, rest pad) | p8S@73(25: rows m<3 real) | p9S@98(25)
__global__ void k_aggregate(int l, const float* __restrict__ tp_w,
                            const float* __restrict__ W0g,
                            const float* __restrict__ W1g,
                            const float* __restrict__ W2g){
  int d=blockIdx.x; int t=threadIdx.x;
  int warp=t>>5, lane=t&31;
  __shared__ float sK[405];
  __shared__ float sw[144];
  __shared__ float xs[2][128];
  __shared__ float sS[2][124];
  __shared__ float sa[480];
  __shared__ int   srow[MAXDEG];
  int deg = g_cnt[d]; if(deg>MAXDEG) deg=MAXDEG;
  if(t<deg) srow[t]=g_row[d*MAXDEG+t];
  for(int i=t;i<405;i+=128) sK[i]=g_K[i];
  for(int i=t;i<144;i+=128) sw[i]=tp_w[l*144+i];
  if(t<124){ sS[0][t]=0.f; sS[1][t]=0.f; }
  // per-thread S-compute config (hoisted)
  int koff=0, sdst=0;
  if(t<5){ koff=1+t*5; sdst=t; }
  else if(t<14){ int x=t-5;  koff=35+(x/3)*15+(x%3)*5;  sdst=8+x; }
  else if(t<29){ int x=t-14; koff=80+(x/3)*15+(x%3)*5;  sdst=20+x; }
  else if(t<34){ int x=t-29; koff=180+x*5;              sdst=48+x; }
  else if(t<49){ int x=t-34; koff=205+(x/5)*25+(x%5)*5; sdst=73+x; }
  else if(t<74){ int x=t-49; koff=280+(x/5)*25+(x%5)*5; sdst=98+x; }
  // per-thread slot config (hoisted)
  int xoff=0, crel=0; bool kb=false;
  if(warp==1){ int u=lane&15; xoff=32+u*3; kb=(lane<16); crel=8; }
  else if(warp==2){ int u=lane>>1; xoff=32+u*3; crel=20+9*(lane&1); }
  else if(warp==3){ int g=lane>>3, u=lane&7; xoff=80+u*5; kb=(g==0);
                    crel=(g==1)?48:((g==2)?73:98); }
  __syncthreads();
  if(t==0 && deg>1){                       // tiny insertion sort (avg deg ~8)
    for(int i=1;i<deg;i++){
      int v2=srow[i]; int j=i-1;
      while(j>=0 && srow[j]>v2){ srow[j+1]=srow[j]; j--; }
      srow[j+1]=v2;
    }
  }
  __syncthreads();
  float a0=0.f,a1=0.f,a2=0.f,a3=0.f,a4=0.f,a5=0.f;
  float v = 0.f;
  if(deg>0) v = load_edge_val(t, srow[0]);
  for(int q=0;q<deg;q++){
    int buf=q&1;
    if(t<125) xs[buf][t]=v;
    __syncthreads();                                    // xs[buf] ready
    if(q+1<deg) v = load_edge_val(t, srow[q+1]);        // prefetch (overlaps)
    if(t<74){
      const float* sh=&xs[buf][120];
      float r = sK[koff]*sh[0];
      r = __fmaf_rn(sK[koff+1], sh[1], r);
      r = __fmaf_rn(sK[koff+2], sh[2], r);
      r = __fmaf_rn(sK[koff+3], sh[3], r);
      r = __fmaf_rn(sK[koff+4], sh[4], r);
      sS[buf][sdst]=r;
    }
    __syncthreads();                                    // sS[buf] ready
    const float* X=xs[buf]; const float* S=sS[buf];
    if(warp==0){
      float x0=X[lane];
      a5 += x0;                                         // p1
      a0=__fmaf_rn(x0,S[0],a0); a1=__fmaf_rn(x0,S[1],a1);
      a2=__fmaf_rn(x0,S[2],a2); a3=__fmaf_rn(x0,S[3],a3);
      a4=__fmaf_rn(x0,S[4],a4);                         // p2
    } else if(warp<3){                                  // uniform 3x3 (p3/p4/p5)
      float b0=X[xoff], b1=X[xoff+1], b2=X[xoff+2];
      const float* cf = kb ? (sK+26) : (S+crel);
      a0=__fmaf_rn(b2,cf[2],__fmaf_rn(b1,cf[1],__fmaf_rn(b0,cf[0],a0)));
      a1=__fmaf_rn(b2,cf[5],__fmaf_rn(b1,cf[4],__fmaf_rn(b0,cf[3],a1)));
      a2=__fmaf_rn(b2,cf[8],__fmaf_rn(b1,cf[7],__fmaf_rn(b0,cf[6],a2)));
    } else {                                            // uniform padded 5x5 (x2 quad)
      float b0=X[xoff],b1=X[xoff+1],b2=X[xoff+2],b3=X[xoff+3],b4=X[xoff+4];
      const float* cf = kb ? (sK+155) : (S+crel);
      a0=__fmaf_rn(b4,cf[4], __fmaf_rn(b3,cf[3], __fmaf_rn(b2,cf[2], __fmaf_rn(b1,cf[1], __fmaf_rn(b0,cf[0], a0)))));
      a1=__fmaf_rn(b4,cf[9], __fmaf_rn(b3,cf[8], __fmaf_rn(b2,cf[7], __fmaf_rn(b1,cf[6], __fmaf_rn(b0,cf[5], a1)))));
      a2=__fmaf_rn(b4,cf[14],__fmaf_rn(b3,cf[13],__fmaf_rn(b2,cf[12],__fmaf_rn(b1,cf[11],__fmaf_rn(b0,cf[10],a2)))));
      a3=__fmaf_rn(b4,cf[19],__fmaf_rn(b3,cf[18],__fmaf_rn(b2,cf[17],__fmaf_rn(b1,cf[16],__fmaf_rn(b0,cf[15],a3)))));
      a4=__fmaf_rn(b4,cf[24],__fmaf_rn(b3,cf[23],__fmaf_rn(b2,cf[22],__fmaf_rn(b1,cf[21],__fmaf_rn(b0,cf[20],a4)))));
    }
  }
  // apply hoisted tp_w, write sa
  if(warp==0){
    int u=lane;
    sa[u] = a5*sK[0]*sw[u];                                          // p1
    float w=sw[32+u]; int base=160+u*5;                              // p2
    sa[base]=a0*w; sa[base+1]=a1*w; sa[base+2]=a2*w; sa[base+3]=a3*w; sa[base+4]=a4*w;
  } else if(warp==1){
    if(lane<16){ int u=lane; float w=sw[64+u]; int base=40+u*3;      // p3
      sa[base]=a0*w; sa[base+1]=a1*w; sa[base+2]=a2*w;
    } else { int u=lane-16; float w=sw[80+u]; int base=40+(16+u)*3;  // p4
      sa[base]=a0*w; sa[base+1]=a1*w; sa[base+2]=a2*w; }
  } else if(warp==2){
    int u=lane>>1, half=lane&1; float w=sw[96+u];                    // p5
    int base=160+(32+u)*5+half*3;
    sa[base]=a0*w; sa[base+1]=a1*w; if(!half) sa[base+2]=a2*w;
  } else {
    int g=lane>>3, u=lane&7;
    if(g==0){ float w=sw[112+u]; int base=160+(48+u)*5;              // p6
      sa[base]=a0*w; sa[base+1]=a1*w; sa[base+2]=a2*w; sa[base+3]=a3*w; sa[base+4]=a4*w;
    } else if(g==1){ sa[32+u]=a0*sw[120+u];                          // p7
    } else if(g==2){ float w=sw[128+u]; int base=40+(32+u)*3;        // p8
      sa[base]=a0*w; sa[base+1]=a1*w; sa[base+2]=a2*w;
    } else { float w=sw[136+u]; int base=160+(56+u)*5;               // p9
      sa[base]=a0*w; sa[base+1]=a1*w; sa[base+2]=a2*w; sa[base+3]=a3*w; sa[base+4]=a4*w; }
  }
  __syncthreads();
  const float* W0=W0g+l*1280; const float* W1=W1g+l*640; const float* W2=W2g+l*512;
  const float inv40 = 0.15811388300841897f;  // 1/sqrt(40)
  if(t<32){
    float s=0.f;
    #pragma unroll
    for(int u=0;u<40;u++) s += sa[u]*__ldg(&W0[u*32+t]);
    g_y0[d*32+t] = s*inv40;
  } else if(t<80){
    int q2=t-32; int v2=q2/3, m=q2-3*v2; float s=0.f;
    #pragma unroll
    for(int u=0;u<40;u++) s += sa[40+u*3+m]*__ldg(&W1[u*16+v2]);
    g_y1[d*48+v2*3+m] = s*inv40;
  } else if(t<120){
    int q2=t-80; int v2=q2/5, o=q2-5*v2; float s=0.f;
    #pragma unroll
    for(int u=0;u<64;u++) s += sa[160+u*5+o]*__ldg(&W2[u*8+v2]);
    g_y2[d*40+v2*5+o] = s*0.125f;       // 1/sqrt(64)
  }
}

// ---------------- BN stats (fp32 Kahan, deterministic) -----------------------
__global__ void k_stats(int l, const float* __restrict__ bw0, const float* __restrict__ bb0,
                        const float* __restrict__ bw1, const float* __restrict__ bw2){
  int b=blockIdx.x, t=threadIdx.x;
  __shared__ float r1[256], r2[256];
  float s1=0.f, c1=0.f, s2=0.f, c2=0.f;   // Kahan accumulators
  #define KADD1(x) { float yy=(x)-c1; float tt=s1+yy; c1=(tt-s1)-yy; s1=tt; }
  #define KADD2(x) { float yy=(x)-c2; float tt=s2+yy; c2=(tt-s2)-yy; s2=tt; }
  if(b<32){
    int c=b;
    for(int n=t;n<NN;n+=256){ float v=g_y0[n*32+c]; KADD1(v); KADD2(v*v); }
  } else if(b<48){
    int c=b-32;
    for(int n=t;n<NN;n+=256){
      #pragma unroll
      for(int m=0;m<3;m++){ float v=g_y1[n*48+c*3+m]; KADD2(v*v); }
    }
  } else {
    int c=b-48;
    for(int n=t;n<NN;n+=256){
      #pragma unroll
      for(int o=0;o<5;o++){ float v=g_y2[n*40+c*5+o]; KADD2(v*v); }
    }
  }
  #undef KADD1
  #undef KADD2
  r1[t]=s1; r2[t]=s2; __syncthreads();
  for(int off=128; off>=1; off>>=1){
    if(t<off){ r1[t]+=r1[t+off]; r2[t]+=r2[t+off]; }
    __syncthreads();
  }
  if(t==0){
    if(b<32){
      int c=b;
      float mu=r1[0]/(float)NN;
      float var=r2[0]/(float)NN - mu*mu;
      float scale = bw0[l*32+c]/sqrtf(var + EPSV);
      g_scale0[c]=scale;
      g_shift0[c]=bb0[l*32+c]-mu*scale;
    } else if(b<48){
      int c=b-32;
      float mean=r2[0]/(float)(NN*3);
      g_scale1[c]=bw1[l*16+c]/sqrtf(mean+EPSV);
    } else {
      int c=b-48;
      float mean=r2[0]/(float)(NN*5);
      g_scale2[c]=bw2[l*8+c]/sqrtf(mean+EPSV);
    }
  }
}

// ---------------- normalize + relu + residual -------------------------------
__global__ void k_update(){
  int t=blockIdx.x*blockDim.x+threadIdx.x;
  if(t>=NN*120) return;
  int n=t/120, r=t-n*120;
  if(r<32){
    int idx=n*32+r;
    float v=g_y0[idx]*g_scale0[r]+g_shift0[r];
    g_x0[idx]+=fmaxf(v,0.f);
  } else if(r<80){
    int q=r-32; int u=q/3; int idx=n*48+q;
    float v=g_y1[idx]*g_scale1[u];
    g_x1[idx]+=fmaxf(v,0.f);
  } else {
    int q=r-80; int u=q/5; int idx=n*40+q;
    float v=g_y2[idx]*g_scale2[u];
    g_x2[idx]+=fmaxf(v,0.f);
  }
}

// ---------------- head MLP ---------------------------------------------------
__global__ void k_head(const float* __restrict__ Wf1, const float* __restrict__ Wf2,
                       const float* __restrict__ bf2, const float* __restrict__ Wf3,
                       const float* __restrict__ bf3, float* __restrict__ out){
  __shared__ float sW1[1024], sW2[512], sb2[16], sW3[32], sb3[2];
  int t=threadIdx.x;
  for(int i=t;i<1024;i+=128) sW1[i]=Wf1[i];
  for(int i=t;i<512;i+=128)  sW2[i]=Wf2[i];
  if(t<16) sb2[t]=bf2[t];
  if(t<32) sW3[t]=Wf3[t];
  if(t<2)  sb3[t]=bf3[t];
  __syncthreads();
  int n=blockIdx.x*128+t;
  float xin[32];
  #pragma unroll
  for(int i=0;i<32;i++) xin[i]=g_x0[n*32+i];
  const float c1=0.1767766952966369f;  // 1/sqrt(32)
  float h1[32];
  #pragma unroll
  for(int j=0;j<32;j++){
    float s=0.f;
    #pragma unroll
    for(int i=0;i<32;i++) s += xin[i]*sW1[i*32+j];
    h1[j]=fmaxf(s*c1,0.f);
  }
  float h2[16];
  #pragma unroll
  for(int k=0;k<16;k++){
    float s=sb2[k];
    #pragma unroll
    for(int j=0;j<32;j++) s += h1[j]*sW2[j*16+k];
    h2[k]=fmaxf(s,0.f);
  }
  #pragma unroll
  for(int m=0;m<2;m++){
    float s=sb3[m];
    #pragma unroll
    for(int k=0;k<16;k++) s += h2[k]*sW3[k*2+m];
    out[n*2+m]=s;
  }
}

// ---------------- launch ------------------------------------------------------
extern "C" void kernel_launch(void* const* d_in, const int* in_sizes, int n_in,
                              void* d_out, int out_size){
  const float* pos    = (const float*)d_in[0];
  const float* W_emb  = (const float*)d_in[1];
  const float* tp_w   = (const float*)d_in[2];
  const float* lin_W0 = (const float*)d_in[3];
  const float* lin_W1 = (const float*)d_in[4];
  const float* lin_W2 = (const float*)d_in[5];
  const float* bn_w0  = (const float*)d_in[6];
  const float* bn_b0  = (const float*)d_in[7];
  const float* bn_w1  = (const float*)d_in[8];
  const float* bn_w2  = (const float*)d_in[9];
  const float* Wf1    = (const float*)d_in[10];
  const float* Wf2    = (const float*)d_in[11];
  const float* bf2    = (const float*)d_in[12];
  const float* Wf3    = (const float*)d_in[13];
  const float* bf3    = (const float*)d_in[14];
  float* out = (float*)d_out;

  k_prep<<<(NN*120+255)/256,256>>>(pos, W_emb);
  k_knn<<<NN/8,256>>>();
  k_edgegeo<<<NE/256,256>>>(pos);
  for(int l=0;l<3;l++){
    k_aggregate<<<NN,128>>>(l, tp_w, lin_W0, lin_W1, lin_W2);
    k_stats<<<56,256>>>(l, bn_w0, bn_b0, bn_w1, bn_w2);
    k_update<<<(NN*120+255)/256,256>>>();
  }
  k_head<<<NN/128,128>>>(Wf1, Wf2, bf2, Wf3, bf3, out);
}

// round 16
// speedup vs baseline: 1.3589x; 1.0214x over previous
#include <cuda_runtime.h>
#include <math.h>

#define NN 8192
#define NEI 8
#define NE (NN*NEI)
#define EPSV 1e-5f
#define MAXDEG 64
#define ECH 8          // edges per chunk
#define TST 144        // per-edge S-table stride (floats)

// ---------------- scratch (static device memory; no runtime alloc) -------------
__device__ float4 g_posq[NN];    // (x, y, z, |p|^2) fp32 (query side)
__device__ float4 g_posq2[NN];   // (2x, 2y, 2z, |p|^2) fp32 (candidate side)
__device__ int    g_nbr[NE];
__device__ float  g_sh2[NE*5];
__device__ int    g_cnt[NN];
__device__ int    g_row[NN*MAXDEG];
__device__ float  g_x0[NN*32];
__device__ float  g_x1[NN*48];
__device__ float  g_x2[NN*40];
__device__ float  g_y0[NN*32];
__device__ float  g_y1[NN*48];
__device__ float  g_y2[NN*40];
__device__ float  g_K[405];
__device__ float  g_scale0[32], g_shift0[32], g_scale1[16], g_scale2[8];

__constant__ float c_FACT[8] = {1.f,1.f,2.f,6.f,24.f,120.f,720.f,5040.f};

// K tensor layout offsets ([o][i][j] row-major per path)
// paths: (0,0,0)@0 sz1 | (0,2,2)@1 sz25 | (1,0,1)@26 sz9 | (1,2,1)@35 sz45 |
// (1,2,2)@80 sz75 | (2,0,2)@155 sz25 | (2,2,0)@180 sz25 | (2,2,1)@205 sz75 | (2,2,2)@280 sz125

// ---------------- K tensor math (fp32, factorial table) -------------------------
__device__ __forceinline__ float cg_coef_f(int j1,int m1,int j2,int m2,int j3,int m3){
  if(m1+m2!=m3 || j3<abs(j1-j2) || j3>j1+j2) return 0.f;
  float pre = sqrtf((2.f*j3+1.f)*c_FACT[j3+j1-j2]*c_FACT[j3-j1+j2]*c_FACT[j1+j2-j3]/c_FACT[j1+j2+j3+1]);
  pre *= sqrtf(c_FACT[j3+m3]*c_FACT[j3-m3]*c_FACT[j1-m1]*c_FACT[j1+m1]*c_FACT[j2-m2]*c_FACT[j2+m2]);
  float s=0.f;
  for(int k=0;k<=j1+j2-j3;k++){
    int d0=k, d1=j1+j2-j3-k, d2=j1-m1-k, d3=j2+m2-k, d4=j3-j2+m1+k, d5=j3-j1-m2+k;
    if(d0<0||d1<0||d2<0||d3<0||d4<0||d5<0) continue;
    float den = c_FACT[d0]*c_FACT[d1]*c_FACT[d2]*c_FACT[d3]*c_FACT[d4]*c_FACT[d5];
    s += ((k&1)? -1.f:1.f)/den;
  }
  return pre*s;
}

__device__ __forceinline__ void q_entry_f(int l,int r,int c,float* re,float* im){
  int a=r-l, b=c-l; *re=0.f; *im=0.f;
  if(a==0 && b==0){ *re=1.f; return; }
  if(abs(a)!=abs(b) || a==0 || b==0) return;
  int m=abs(a); float s=0.70710678118654752f; float sgn=(m&1)? -1.f:1.f;
  if(a==m && b==m)       *re = sgn*s;
  else if(a==m && b==-m) *re = s;
  else if(a==-m && b==m) *im = -sgn*s;
  else                   *im = s;
}

__device__ void initK_block(int p, int t){
  const int L1[9]={0,0,1,1,1,2,2,2,2};
  const int L2[9]={0,2,0,2,2,0,2,2,2};
  const int L3[9]={0,2,1,1,2,2,0,1,2};
  const int OFF[9]={0,1,26,35,80,155,180,205,280};
  int l1=L1[p], l2=L2[p], l3=L3[p];
  int d1=2*l1+1, d2=2*l2+1, d3=2*l3+1;
  int tot=d1*d2*d3;
  __shared__ float s_re[125], s_im[125];
  __shared__ int s_useim;
  float re=0.f, im=0.f;
  if(t<tot){
    int c=t/(d1*d2); int rem=t-(c*d1*d2); int a=rem/d2; int b=rem-a*d2;
    for(int C=0;C<d3;C++){
      float q3r,q3i; q_entry_f(l3,c,C,&q3r,&q3i); q3i=-q3i;  // conj
      if(q3r==0.f && q3i==0.f) continue;
      for(int A=0;A<d1;A++){
        float q1r,q1i; q_entry_f(l1,a,A,&q1r,&q1i);
        if(q1r==0.f && q1i==0.f) continue;
        for(int B=0;B<d2;B++){
          float q2r,q2i; q_entry_f(l2,b,B,&q2r,&q2i);
          if(q2r==0.f && q2i==0.f) continue;
          float cgv = cg_coef_f(l1,A-l1,l2,B-l2,l3,C-l3);
          if(cgv==0.f) continue;
          float xr=q3r*q1r-q3i*q1i, xi=q3r*q1i+q3i*q1r;
          float yr=xr*q2r-xi*q2i,  yi=xr*q2i+xi*q2r;
          re += yr*cgv; im += yi*cgv;
        }
      }
    }
    s_re[t]=re; s_im[t]=im;
  }
  __syncthreads();
  if(t==0){
    float mr=0.f, mi=0.f;
    for(int k=0;k<tot;k++){ mr=fmaxf(mr,fabsf(s_re[k])); mi=fmaxf(mi,fabsf(s_im[k])); }
    s_useim = (mi>mr)?1:0;
  }
  __syncthreads();
  if(t<tot) g_K[OFF[p]+t] = s_useim ? s_im[t] : s_re[t];
}

// ---------------- prep (posq + cnt + x init + K init, fused) -----------------
__global__ void k_prep(const float* __restrict__ pos, const float* __restrict__ W_emb){
  int t=blockIdx.x*blockDim.x+threadIdx.x;
  if(t<NN){
    float x=pos[t*3+0], y=pos[t*3+1], z=pos[t*3+2];
    float sq = __fadd_rn(__fadd_rn(__fmul_rn(x,x),__fmul_rn(y,y)),__fmul_rn(z,z));
    float4 q;  q.x=x;      q.y=y;      q.z=z;      q.w=sq;  g_posq[t]=q;
    float4 q2; q2.x=2.f*x; q2.y=2.f*y; q2.z=2.f*z; q2.w=sq; g_posq2[t]=q2;
    g_cnt[t]=0;
  }
  if(t < NN*32)       g_x0[t] = W_emb[t & 31];
  else if(t < NN*80)  g_x1[t-NN*32] = 0.f;
  else if(t < NN*120) g_x2[t-NN*80] = 0.f;
  if(blockIdx.x < 9) initK_block(blockIdx.x, threadIdx.x);
}

// ---------------- KNN: warp-cooperative replicated top-9 ---------------------
__device__ __forceinline__ void topk_insert(float (&bv)[9], int (&bi)[9], float v, int j){
  float cv=v; int ci=j;
  #pragma unroll
  for(int k=0;k<9;k++){
    bool sw = (cv<bv[k]) || (cv==bv[k] && ci<bi[k]);
    float tv=bv[k]; int ti=bi[k];
    if(sw){ bv[k]=cv; bi[k]=ci; cv=tv; ci=ti; }
  }
}

__global__ void __launch_bounds__(256) k_knn(){
  int warp = threadIdx.x>>5, lane = threadIdx.x&31;
  int i = blockIdx.x*8 + warp;
  float4 q = g_posq[i];
  float bv[9]; int bi[9];
  #pragma unroll
  for(int k=0;k<9;k++){ bv[k]=INFINITY; bi[k]=0x7fffffff; }
  __shared__ float4 tile[256];
  for(int jt=0; jt<NN; jt+=256){
    __syncthreads();
    tile[threadIdx.x] = g_posq2[jt+threadIdx.x];
    __syncthreads();
    #pragma unroll
    for(int k=0;k<8;k++){
      int jj = lane + k*32;
      float4 p = tile[jj];
      float dot2 = __fmaf_rn(q.z, p.z, __fmaf_rn(q.y, p.y, __fmul_rn(q.x, p.x)));
      float d2   = __fsub_rn(__fadd_rn(q.w, p.w), dot2);
      unsigned mask = __ballot_sync(0xffffffffu, d2 <= bv[8]);
      while(mask){
        int b = __ffs(mask)-1; mask &= mask-1;
        float v = __shfl_sync(0xffffffffu, d2, b);
        int  id = jt + b + k*32;
        if(v < bv[8] || (v==bv[8] && id < bi[8]))
          topk_insert(bv, bi, v, id);
      }
    }
  }
  if(lane==0){
    #pragma unroll
    for(int r=0;r<8;r++) g_nbr[i*NEI+r] = bi[1+r];   // drop slot 0 (self)
  }
}

// ---------------- edge geometry (sh2) + fixed-capacity row push --------------
__global__ void k_edgegeo(const float* __restrict__ pos){
  int e=blockIdx.x*blockDim.x+threadIdx.x;
  if(e>=NE) return;
  int s=e>>3; int d=g_nbr[e];
  float ex=pos[d*3+0]-pos[s*3+0];
  float ey=pos[d*3+1]-pos[s*3+1];
  float ez=pos[d*3+2]-pos[s*3+2];
  float nrm = sqrtf(ex*ex+ey*ey+ez*ez) + 1e-12f;
  float x=ex/nrm, y=ey/nrm, z=ez/nrm;
  const float s15 = 3.8729833462074170f;  // sqrt(15)
  const float s5  = 2.2360679774997896f;  // sqrt(5)
  g_sh2[e*5+0] = s15*x*y;
  g_sh2[e*5+1] = s15*y*z;
  g_sh2[e*5+2] = 0.5f*s5*(3.f*z*z-1.f);
  g_sh2[e*5+3] = s15*x*z;
  g_sh2[e*5+4] = 0.5f*s15*(x*x-y*y);
  int slot = atomicAdd(&g_cnt[d],1);
  if(slot < MAXDEG) g_row[d*MAXDEG+slot] = e;
}

__device__ __forceinline__ float load_edge_val(int t, int e){
  int s=e>>3;
  if(t<32)  return g_x0[s*32+t];
  if(t<80)  return g_x1[s*48+(t-32)];
  if(t<120) return g_x2[s*40+(t-80)];
  if(t<125) return g_sh2[e*5+(t-120)];
  return 0.f;
}

// ---------------- aggregate + linear: balanced halves, chunked edges ---------
// Block = 1 dst node, 128 threads = 4 warps, per edge:
//  W0: x0 row u=lane (p1:1 + p2:5) + p5 half (u5=lane&15, half=lane>>4): 9  => 15 FMA
//  W1: p3 (lanes<16, coef=K) / p4 : 3x3                                   => 9
//  W2: x2-quad half o0-2 (g=lane>>3, u=lane&7)                            => 15
//  W3: x2-quad half o3-4                                                  => 10
// Per-edge S table (stride TST, zero-padded):
//  P2@0(5) | P4@8(9) | P5@20(18; real 15) | Q@40(100): g0=p6 const 40..64,
//  g1=p7 65..89 (real 65..69), g2=p8 90..114 (real 90..104), g3=p9 115..139
__global__ void k_aggregate(int l, const float* __restrict__ tp_w,
                            const float* __restrict__ W0g,
                            const float* __restrict__ W1g,
                            const float* __restrict__ W2g){
  int d=blockIdx.x; int t=threadIdx.x;
  int warp=t>>5, lane=t&31;
  __shared__ float sK[405];
  __shared__ float sw[144];
  __shared__ float xs[ECH][128];
  __shared__ float sS[ECH*TST];
  __shared__ float sa[480];
  __shared__ int   srow[MAXDEG];
  __shared__ int   skoff[74], ssdst[74];
  int deg = g_cnt[d]; if(deg>MAXDEG) deg=MAXDEG;
  if(t<deg) srow[t]=g_row[d*MAXDEG+t];
  for(int i=t;i<405;i+=128) sK[i]=g_K[i];
  for(int i=t;i<144;i+=128) sw[i]=tp_w[l*144+i];
  for(int i=t;i<ECH*TST;i+=128) sS[i]=0.f;
  // S-producer config tables
  if(t<74){
    int koff, sdst;
    if(t<5){ koff=1+t*5; sdst=t; }
    else if(t<14){ int x=t-5;  koff=35+(x/3)*15+(x%3)*5;  sdst=8+x; }
    else if(t<29){ int x=t-14; koff=80+(x/3)*15+(x%3)*5;  sdst=20+x; }
    else if(t<34){ int x=t-29; koff=180+x*5;              sdst=65+x; }
    else if(t<49){ int x=t-34; koff=205+(x/5)*25+(x%5)*5; sdst=90+x; }
    else         { int x=t-49; koff=280+(x/5)*25+(x%5)*5; sdst=115+x; }
    skoff[t]=koff; ssdst[t]=sdst;
  }
  __syncthreads();
  // p6 constant block into every edge slot (after zero fill)
  for(int i=t;i<ECH*25;i+=128){
    int e=i/25, k=i-e*25;
    sS[e*TST+40+k]=sK[155+k];
  }
  if(t==0 && deg>1){                       // tiny insertion sort (avg deg ~8)
    for(int i=1;i<deg;i++){
      int v2=srow[i]; int j=i-1;
      while(j>=0 && srow[j]>v2){ srow[j+1]=srow[j]; j--; }
      srow[j+1]=v2;
    }
  }
  __syncthreads();
  // per-thread accumulate config (hoisted)
  int xoff=0, g=0, u=0;
  if(warp==1){ u=lane&15; xoff=32+u*3; }
  else if(warp>=2){ g=lane>>3; u=lane&7; xoff=80+u*5; }
  float a0=0.f,a1=0.f,a2=0.f,a3=0.f,a4=0.f,aP1=0.f,c0=0.f,c1=0.f,c2=0.f;
  for(int cb=0; cb<deg; cb+=ECH){
    int ec = deg-cb; if(ec>ECH) ec=ECH;
    // stage chunk (coalesced LDG, MLP up to 8)
    float vv[ECH];
    #pragma unroll
    for(int e=0;e<ECH;e++) if(e<ec) vv[e]=load_edge_val(t, srow[cb+e]);
    __syncthreads();   // previous chunk's tables fully consumed
    if(t<125){
      #pragma unroll
      for(int e=0;e<ECH;e++) if(e<ec) xs[e][t]=vv[e];
    }
    __syncthreads();
    // S tables for all edges in chunk (flattened tasks)
    for(int tau=t; tau<ec*74; tau+=128){
      int e=tau/74, j=tau-74*e;
      int koff=skoff[j];
      const float* sh=&xs[e][120];
      float r = sK[koff]*sh[0];
      r = __fmaf_rn(sK[koff+1], sh[1], r);
      r = __fmaf_rn(sK[koff+2], sh[2], r);
      r = __fmaf_rn(sK[koff+3], sh[3], r);
      r = __fmaf_rn(sK[koff+4], sh[4], r);
      sS[e*TST+ssdst[j]]=r;
    }
    __syncthreads();
    // accumulate, no barriers inside
    for(int e=0;e<ec;e++){
      const float* X=xs[e];
      const float* T=&sS[e*TST];
      if(warp==0){
        float x0v=X[lane];
        aP1 += x0v;                                       // p1
        a0=__fmaf_rn(x0v,T[0],a0); a1=__fmaf_rn(x0v,T[1],a1);
        a2=__fmaf_rn(x0v,T[2],a2); a3=__fmaf_rn(x0v,T[3],a3);
        a4=__fmaf_rn(x0v,T[4],a4);                        // p2
        int u5=lane&15, half=lane>>4;
        const float* cf=T+20+9*half;
        const float* x1=&X[32+u5*3];
        float b0=x1[0],b1=x1[1],b2=x1[2];
        c0=__fmaf_rn(b2,cf[2],__fmaf_rn(b1,cf[1],__fmaf_rn(b0,cf[0],c0)));
        c1=__fmaf_rn(b2,cf[5],__fmaf_rn(b1,cf[4],__fmaf_rn(b0,cf[3],c1)));
        c2=__fmaf_rn(b2,cf[8],__fmaf_rn(b1,cf[7],__fmaf_rn(b0,cf[6],c2)));  // p5 half
      } else if(warp==1){                                 // p3/p4
        float b0=X[xoff],b1=X[xoff+1],b2=X[xoff+2];
        const float* cf = (lane<16)? (sK+26) : (T+8);
        c0=__fmaf_rn(b2,cf[2],__fmaf_rn(b1,cf[1],__fmaf_rn(b0,cf[0],c0)));
        c1=__fmaf_rn(b2,cf[5],__fmaf_rn(b1,cf[4],__fmaf_rn(b0,cf[3],c1)));
        c2=__fmaf_rn(b2,cf[8],__fmaf_rn(b1,cf[7],__fmaf_rn(b0,cf[6],c2)));
      } else if(warp==2){                                 // quad o0-2
        float b0=X[xoff],b1=X[xoff+1],b2=X[xoff+2],b3=X[xoff+3],b4=X[xoff+4];
        const float* cf = T+40+g*25;
        c0=__fmaf_rn(b4,cf[4], __fmaf_rn(b3,cf[3], __fmaf_rn(b2,cf[2], __fmaf_rn(b1,cf[1], __fmaf_rn(b0,cf[0], c0)))));
        c1=__fmaf_rn(b4,cf[9], __fmaf_rn(b3,cf[8], __fmaf_rn(b2,cf[7], __fmaf_rn(b1,cf[6], __fmaf_rn(b0,cf[5], c1)))));
        c2=__fmaf_rn(b4,cf[14],__fmaf_rn(b3,cf[13],__fmaf_rn(b2,cf[12],__fmaf_rn(b1,cf[11],__fmaf_rn(b0,cf[10],c2)))));
      } else {                                            // quad o3-4
        float b0=X[xoff],b1=X[xoff+1],b2=X[xoff+2],b3=X[xoff+3],b4=X[xoff+4];
        const float* cf = T+40+g*25+15;
        c0=__fmaf_rn(b4,cf[4],__fmaf_rn(b3,cf[3],__fmaf_rn(b2,cf[2],__fmaf_rn(b1,cf[1],__fmaf_rn(b0,cf[0],c0)))));
        c1=__fmaf_rn(b4,cf[9],__fmaf_rn(b3,cf[8],__fmaf_rn(b2,cf[7],__fmaf_rn(b1,cf[6],__fmaf_rn(b0,cf[5],c1)))));
      }
    }
  }
  // apply hoisted tp_w, write sa
  if(warp==0){
    int u0=lane;
    sa[u0] = aP1*sK[0]*sw[u0];                                       // p1
    float w=sw[32+u0]; int base=160+u0*5;                            // p2
    sa[base]=a0*w; sa[base+1]=a1*w; sa[base+2]=a2*w; sa[base+3]=a3*w; sa[base+4]=a4*w;
    int u5=lane&15, half=lane>>4; float w5=sw[96+u5];                // p5 halves
    int b5=160+(32+u5)*5;
    if(half==0){ sa[b5]=c0*w5; sa[b5+1]=c1*w5; sa[b5+2]=c2*w5; }
    else       { sa[b5+3]=c0*w5; sa[b5+4]=c1*w5; }
  } else if(warp==1){
    int u1=lane&15;
    if(lane<16){ float w=sw[64+u1]; int base=40+u1*3;                // p3
      sa[base]=c0*w; sa[base+1]=c1*w; sa[base+2]=c2*w;
    } else { float w=sw[80+u1]; int base=40+(16+u1)*3;               // p4
      sa[base]=c0*w; sa[base+1]=c1*w; sa[base+2]=c2*w; }
  } else if(warp==2){                                                // quad o0-2
    if(g==0){ float w=sw[112+u]; int base=160+(48+u)*5;              // p6
      sa[base]=c0*w; sa[base+1]=c1*w; sa[base+2]=c2*w;
    } else if(g==1){ sa[32+u]=c0*sw[120+u];                          // p7 (o0 only)
    } else if(g==2){ float w=sw[128+u]; int base=40+(32+u)*3;        // p8
      sa[base]=c0*w; sa[base+1]=c1*w; sa[base+2]=c2*w;
    } else { float w=sw[136+u]; int base=160+(56+u)*5;               // p9
      sa[base]=c0*w; sa[base+1]=c1*w; sa[base+2]=c2*w; }
  } else {                                                           // quad o3-4
    if(g==0){ float w=sw[112+u]; int base=160+(48+u)*5;
      sa[base+3]=c0*w; sa[base+4]=c1*w;
    } else if(g==3){ float w=sw[136+u]; int base=160+(56+u)*5;
      sa[base+3]=c0*w; sa[base+4]=c1*w; }
    // g1/g2 lanes: pad-only, nothing to write
  }
  __syncthreads();
  const float* W0=W0g+l*1280; const float* W1=W1g+l*640; const float* W2=W2g+l*512;
  const float inv40 = 0.15811388300841897f;  // 1/sqrt(40)
  if(t<32){
    float s=0.f;
    #pragma unroll
    for(int uu=0;uu<40;uu++) s += sa[uu]*__ldg(&W0[uu*32+t]);
    g_y0[d*32+t] = s*inv40;
  } else if(t<80){
    int q2=t-32; int v2=q2/3, m=q2-3*v2; float s=0.f;
    #pragma unroll
    for(int uu=0;uu<40;uu++) s += sa[40+uu*3+m]*__ldg(&W1[uu*16+v2]);
    g_y1[d*48+v2*3+m] = s*inv40;
  } else if(t<120){
    int q2=t-80; int v2=q2/5, o=q2-5*v2; float s=0.f;
    #pragma unroll
    for(int uu=0;uu<64;uu++) s += sa[160+uu*5+o]*__ldg(&W2[uu*8+v2]);
    g_y2[d*40+v2*5+o] = s*0.125f;       // 1/sqrt(64)
  }
}

// ---------------- BN stats (fp32 Kahan, deterministic) -----------------------
__global__ void k_stats(int l, const float* __restrict__ bw0, const float* __restrict__ bb0,
                        const float* __restrict__ bw1, const float* __restrict__ bw2){
  int b=blockIdx.x, t=threadIdx.x;
  __shared__ float r1[256], r2[256];
  float s1=0.f, c1=0.f, s2=0.f, c2=0.f;   // Kahan accumulators
  #define KADD1(x) { float yy=(x)-c1; float tt=s1+yy; c1=(tt-s1)-yy; s1=tt; }
  #define KADD2(x) { float yy=(x)-c2; float tt=s2+yy; c2=(tt-s2)-yy; s2=tt; }
  if(b<32){
    int c=b;
    for(int n=t;n<NN;n+=256){ float v=g_y0[n*32+c]; KADD1(v); KADD2(v*v); }
  } else if(b<48){
    int c=b-32;
    for(int n=t;n<NN;n+=256){
      #pragma unroll
      for(int m=0;m<3;m++){ float v=g_y1[n*48+c*3+m]; KADD2(v*v); }
    }
  } else {
    int c=b-48;
    for(int n=t;n<NN;n+=256){
      #pragma unroll
      for(int o=0;o<5;o++){ float v=g_y2[n*40+c*5+o]; KADD2(v*v); }
    }
  }
  #undef KADD1
  #undef KADD2
  r1[t]=s1; r2[t]=s2; __syncthreads();
  for(int off=128; off>=1; off>>=1){
    if(t<off){ r1[t]+=r1[t+off]; r2[t]+=r2[t+off]; }
    __syncthreads();
  }
  if(t==0){
    if(b<32){
      int c=b;
      float mu=r1[0]/(float)NN;
      float var=r2[0]/(float)NN - mu*mu;
      float scale = bw0[l*32+c]/sqrtf(var + EPSV);
      g_scale0[c]=scale;
      g_shift0[c]=bb0[l*32+c]-mu*scale;
    } else if(b<48){
      int c=b-32;
      float mean=r2[0]/(float)(NN*3);
      g_scale1[c]=bw1[l*16+c]/sqrtf(mean+EPSV);
    } else {
      int c=b-48;
      float mean=r2[0]/(float)(NN*5);
      g_scale2[c]=bw2[l*8+c]/sqrtf(mean+EPSV);
    }
  }
}

// ---------------- normalize + relu + residual -------------------------------
__global__ void k_update(){
  int t=blockIdx.x*blockDim.x+threadIdx.x;
  if(t>=NN*120) return;
  int n=t/120, r=t-n*120;
  if(r<32){
    int idx=n*32+r;
    float v=g_y0[idx]*g_scale0[r]+g_shift0[r];
    g_x0[idx]+=fmaxf(v,0.f);
  } else if(r<80){
    int q=r-32; int u=q/3; int idx=n*48+q;
    float v=g_y1[idx]*g_scale1[u];
    g_x1[idx]+=fmaxf(v,0.f);
  } else {
    int q=r-80; int u=q/5; int idx=n*40+q;
    float v=g_y2[idx]*g_scale2[u];
    g_x2[idx]+=fmaxf(v,0.f);
  }
}

// ---------------- head MLP ---------------------------------------------------
__global__ void k_head(const float* __restrict__ Wf1, const float* __restrict__ Wf2,
                       const float* __restrict__ bf2, const float* __restrict__ Wf3,
                       const float* __restrict__ bf3, float* __restrict__ out){
  __shared__ float sW1[1024], sW2[512], sb2[16], sW3[32], sb3[2];
  int t=threadIdx.x;
  for(int i=t;i<1024;i+=128) sW1[i]=Wf1[i];
  for(int i=t;i<512;i+=128)  sW2[i]=Wf2[i];
  if(t<16) sb2[t]=bf2[t];
  if(t<32) sW3[t]=Wf3[t];
  if(t<2)  sb3[t]=bf3[t];
  __syncthreads();
  int n=blockIdx.x*128+t;
  float xin[32];
  #pragma unroll
  for(int i=0;i<32;i++) xin[i]=g_x0[n*32+i];
  const float c1=0.1767766952966369f;  // 1/sqrt(32)
  float h1[32];
  #pragma unroll
  for(int j=0;j<32;j++){
    float s=0.f;
    #pragma unroll
    for(int i=0;i<32;i++) s += xin[i]*sW1[i*32+j];
    h1[j]=fmaxf(s*c1,0.f);
  }
  float h2[16];
  #pragma unroll
  for(int k=0;k<16;k++){
    float s=sb2[k];
    #pragma unroll
    for(int j=0;j<32;j++) s += h1[j]*sW2[j*16+k];
    h2[k]=fmaxf(s,0.f);
  }
  #pragma unroll
  for(int m=0;m<2;m++){
    float s=sb3[m];
    #pragma unroll
    for(int k=0;k<16;k++) s += h2[k]*sW3[k*2+m];
    out[n*2+m]=s;
  }
}

// ---------------- launch ------------------------------------------------------
extern "C" void kernel_launch(void* const* d_in, const int* in_sizes, int n_in,
                              void* d_out, int out_size){
  const float* pos    = (const float*)d_in[0];
  const float* W_emb  = (const float*)d_in[1];
  const float* tp_w   = (const float*)d_in[2];
  const float* lin_W0 = (const float*)d_in[3];
  const float* lin_W1 = (const float*)d_in[4];
  const float* lin_W2 = (const float*)d_in[5];
  const float* bn_w0  = (const float*)d_in[6];
  const float* bn_b0  = (const float*)d_in[7];
  const float* bn_w1  = (const float*)d_in[8];
  const float* bn_w2  = (const float*)d_in[9];
  const float* Wf1    = (const float*)d_in[10];
  const float* Wf2    = (const float*)d_in[11];
  const float* bf2    = (const float*)d_in[12];
  const float* Wf3    = (const float*)d_in[13];
  const float* bf3    = (const float*)d_in[14];
  float* out = (float*)d_out;

  k_prep<<<(NN*120+255)/256,256>>>(pos, W_emb);
  k_knn<<<NN/8,256>>>();
  k_edgegeo<<<NE/256,256>>>(pos);
  for(int l=0;l<3;l++){
    k_aggregate<<<NN,128>>>(l, tp_w, lin_W0, lin_W1, lin_W2);
    k_stats<<<56,256>>>(l, bn_w0, bn_b0, bn_w1, bn_w2);
    k_update<<<(NN*120+255)/256,256>>>();
  }
  k_head<<<NN/128,128>>>(Wf1, Wf2, bf2, Wf3, bf3, out);
}